// round 5
// baseline (speedup 1.0000x reference)
#include <cuda_runtime.h>
#include <cuda_fp16.h>
#include <math.h>
#include <stdint.h>

// Problem constants
#define NR 8192
#define DD 1024
#define ITERS 20
#define INV_TEMP 20.0f

// iteration-1 column pass chunking
#define COL_CHUNKS 64
#define ROWS_PER_CHUNK (NR / COL_CHUNKS)

// fast fused Sinkhorn iteration
#define FRPB 16
#define FNBLK (NR / FRPB)   // 512

// HMMA tiling: BM=128, BN=128, BK=32, 8 warps (2 M x 4 N), warp tile 64x32
#define HBK 32
#define ROWB 80                       // padded row stride in bytes (32 halfs + 8 pad)
#define TILEB (128 * ROWB)            // 10240 B per operand tile
#define BUFB (4 * TILEB)              // 40960 B per stage (Ahi,Alo,Bhi,Blo)
#define SMEM_HMMA (2 * BUFB)          // 81920 B double buffered

// ---------------- device scratch (static, no allocation) ----------------
__device__ float g_scores[(size_t)NR * NR];   // 256 MB
__device__ __half g_x_hi[(size_t)NR * DD];
__device__ __half g_x_lo[(size_t)NR * DD];
__device__ __half g_h_hi[(size_t)NR * DD];
__device__ __half g_h_lo[(size_t)NR * DD];
__device__ __half g_a_hi[(size_t)NR * DD];
__device__ __half g_a_lo[(size_t)NR * DD];
__device__ __half g_b_hi[(size_t)NR * DD];
__device__ __half g_b_lo[(size_t)NR * DD];
__device__ __half g_w1_hi[(size_t)DD * DD];
__device__ __half g_w1_lo[(size_t)DD * DD];
__device__ __half g_w2_hi[(size_t)DD * DD];
__device__ __half g_w2_lo[(size_t)DD * DD];
__device__ float g_r[NR];
__device__ float g_c[NR];
__device__ float g_pm[(size_t)COL_CHUNKS * NR];
__device__ float g_ps[(size_t)COL_CHUNKS * NR];
__device__ float g_part[(size_t)FNBLK * NR];  // 16 MB

// ---------------- small helpers ----------------
__device__ __forceinline__ uint32_t smem_to_u32(const void* smem_ptr) {
    uint32_t addr;
    asm("{ .reg .u64 tmp; cvta.to.shared.u64 tmp, %1; cvt.u32.u64 %0, tmp; }"
        : "=r"(addr) : "l"(smem_ptr));
    return addr;
}
__device__ __forceinline__ void cp16(uint32_t saddr, const void* g) {
    asm volatile("cp.async.cg.shared.global [%0], [%1], 16;" :: "r"(saddr), "l"(g));
}
__device__ __forceinline__ void cp_commit() {
    asm volatile("cp.async.commit_group;");
}
template <int N> __device__ __forceinline__ void cp_wait() {
    asm volatile("cp.async.wait_group %0;" :: "n"(N));
}
__device__ __forceinline__ void ldsm_x4(uint32_t* r, uint32_t addr) {
    asm volatile("ldmatrix.sync.aligned.m8n8.x4.shared.b16 {%0,%1,%2,%3}, [%4];"
                 : "=r"(r[0]), "=r"(r[1]), "=r"(r[2]), "=r"(r[3]) : "r"(addr));
}
__device__ __forceinline__ void ldsm_x2(uint32_t* r, uint32_t addr) {
    asm volatile("ldmatrix.sync.aligned.m8n8.x2.shared.b16 {%0,%1}, [%2];"
                 : "=r"(r[0]), "=r"(r[1]) : "r"(addr));
}
__device__ __forceinline__ void mma16816(float* c, const uint32_t* a, const uint32_t* b) {
    asm volatile(
        "mma.sync.aligned.m16n8k16.row.col.f32.f16.f16.f32 "
        "{%0,%1,%2,%3}, {%4,%5,%6,%7}, {%8,%9}, {%0,%1,%2,%3};"
        : "+f"(c[0]), "+f"(c[1]), "+f"(c[2]), "+f"(c[3])
        : "r"(a[0]), "r"(a[1]), "r"(a[2]), "r"(a[3]), "r"(b[0]), "r"(b[1]));
}
__device__ __forceinline__ float gelu_exact(float x) {
    return 0.5f * x * (1.0f + erff(x * 0.70710678118654752440f));
}
__device__ __forceinline__ void lse_add(float& m, float& s, float v) {
    if (v <= m) { s += __expf(v - m); }
    else        { s = s * __expf(m - v) + 1.0f; m = v; }
}
__device__ __forceinline__ void lse_merge(float& m1, float& s1, float m2, float s2) {
    if (m2 == -INFINITY) return;
    if (m1 == -INFINITY) { m1 = m2; s1 = s2; return; }
    if (m2 <= m1) { s1 += s2 * __expf(m2 - m1); }
    else { s1 = s1 * __expf(m1 - m2) + s2; m1 = m2; }
}

// ---------------- HMMA GEMM: C = epilogue(scale*(A @ B^T) [+ bias]) ----------------
// A: [M, K] hi/lo half splits (row-major, K contiguous)
// B: [N, K] hi/lo half splits (row-major, K contiguous)
// 2-split product: hh + hl + lh (fp32 accumulate)
// __launch_bounds__(256, 2): cap at 128 regs so 2 CTAs co-reside per SM and
// overlap each other's ldsm/sync bubbles on the tensor pipe.
template <int ACT, int OUT_SPLIT>
__global__ __launch_bounds__(256, 2)
void hmma_kernel(const __half* __restrict__ Ah, const __half* __restrict__ Al,
                 const __half* __restrict__ Bh, const __half* __restrict__ Bl,
                 const float* __restrict__ bias,
                 float* __restrict__ Cf, __half* __restrict__ Chi, __half* __restrict__ Clo,
                 int ldc, int Kdim, float scale)
{
    extern __shared__ __align__(16) char smem[];
    const uint32_t sbase = smem_to_u32(smem);
    const int tid  = threadIdx.x;
    const int warp = tid >> 5;
    const int lane = tid & 31;
    const int wm = warp >> 2;       // 0..1 (64-row slab)
    const int wn = warp & 3;        // 0..3 (32-col slab)

    const int m0 = blockIdx.y * 128;
    const int n0 = blockIdx.x * 128;

    const __half* gsrc0 = Ah + (size_t)m0 * Kdim;
    const __half* gsrc1 = Al + (size_t)m0 * Kdim;
    const __half* gsrc2 = Bh + (size_t)n0 * Kdim;
    const __half* gsrc3 = Bl + (size_t)n0 * Kdim;

    float acc[4][4][4];
#pragma unroll
    for (int i = 0; i < 4; i++)
#pragma unroll
        for (int j = 0; j < 4; j++)
#pragma unroll
            for (int k = 0; k < 4; k++) acc[i][j][k] = 0.0f;

    const int nTiles = Kdim / HBK;

    // ---- async tile loader: 8 x 16B chunks per thread per stage ----
    auto issue = [&](int buf, int kt) {
#pragma unroll
        for (int j = 0; j < 8; j++) {
            const int tile = j >> 1;
            const int qq = (j & 1) * 256 + tid;
            const int r = qq >> 2;
            const int cch = qq & 3;
            const __half* g;
            if      (tile == 0) g = gsrc0 + (size_t)r * Kdim + kt + cch * 8;
            else if (tile == 1) g = gsrc1 + (size_t)r * Kdim + kt + cch * 8;
            else if (tile == 2) g = gsrc2 + (size_t)r * Kdim + kt + cch * 8;
            else                g = gsrc3 + (size_t)r * Kdim + kt + cch * 8;
            cp16(sbase + buf * BUFB + tile * TILEB + r * ROWB + cch * 16, g);
        }
        cp_commit();
    };

    issue(0, 0);

    // per-lane ldmatrix address components (loop invariant)
    const int arow = wm * 64 + (lane & 15);
    const int akof = (lane >> 4) * 8;
    const int brow = wn * 32 + (lane & 7);
    const int bkof = ((lane >> 3) & 1) * 8;

    for (int t = 0; t < nTiles; ++t) {
        if (t + 1 < nTiles) {
            issue((t + 1) & 1, (t + 1) * HBK);
            cp_wait<1>();
        } else {
            cp_wait<0>();
        }
        __syncthreads();

        const uint32_t bufb = sbase + (t & 1) * BUFB;
        const uint32_t aBhi = bufb;
        const uint32_t aBlo = bufb + TILEB;
        const uint32_t bBhi = bufb + 2 * TILEB;
        const uint32_t bBlo = bufb + 3 * TILEB;

#pragma unroll
        for (int ks = 0; ks < HBK; ks += 16) {
            uint32_t bh[4][2];
#pragma unroll
            for (int bn = 0; bn < 4; bn++) {
                const uint32_t off = (uint32_t)(brow + bn * 8) * ROWB + (ks + bkof) * 2;
                ldsm_x2(bh[bn], bBhi + off);
            }
            uint32_t af[4][4];
#pragma unroll
            for (int am = 0; am < 4; am++) {
                const uint32_t off = (uint32_t)(arow + am * 16) * ROWB + (ks + akof) * 2;
                ldsm_x4(af[am], aBhi + off);
            }
            // hi * hi
#pragma unroll
            for (int am = 0; am < 4; am++)
#pragma unroll
                for (int bn = 0; bn < 4; bn++)
                    mma16816(acc[am][bn], af[am], bh[bn]);
            // hi * lo
            {
                uint32_t bl[4][2];
#pragma unroll
                for (int bn = 0; bn < 4; bn++) {
                    const uint32_t off = (uint32_t)(brow + bn * 8) * ROWB + (ks + bkof) * 2;
                    ldsm_x2(bl[bn], bBlo + off);
                }
#pragma unroll
                for (int am = 0; am < 4; am++)
#pragma unroll
                    for (int bn = 0; bn < 4; bn++)
                        mma16816(acc[am][bn], af[am], bl[bn]);
            }
            // lo * hi (reuse af registers)
#pragma unroll
            for (int am = 0; am < 4; am++) {
                const uint32_t off = (uint32_t)(arow + am * 16) * ROWB + (ks + akof) * 2;
                ldsm_x4(af[am], aBlo + off);
            }
#pragma unroll
            for (int am = 0; am < 4; am++)
#pragma unroll
                for (int bn = 0; bn < 4; bn++)
                    mma16816(acc[am][bn], af[am], bh[bn]);
        }
        __syncthreads();
    }

    // ---- epilogue ----
#pragma unroll
    for (int am = 0; am < 4; am++) {
#pragma unroll
        for (int bn = 0; bn < 4; bn++) {
            const int row = m0 + wm * 64 + am * 16 + (lane >> 2);
            const int col = n0 + wn * 32 + bn * 8 + (lane & 3) * 2;
            float v[4];
#pragma unroll
            for (int k = 0; k < 4; k++) v[k] = acc[am][bn][k] * scale;
            if (bias) {
                const float bx = bias[col], by = bias[col + 1];
                v[0] += bx; v[1] += by; v[2] += bx; v[3] += by;
            }
            if (ACT == 1) {
#pragma unroll
                for (int k = 0; k < 4; k++) v[k] = gelu_exact(v[k]);
            }
            if (OUT_SPLIT == 1) {
#pragma unroll
                for (int half_row = 0; half_row < 2; half_row++) {
                    const size_t base = (size_t)(row + half_row * 8) * ldc + col;
                    const float v0 = v[half_row * 2], v1 = v[half_row * 2 + 1];
                    const __half h0 = __float2half_rn(v0);
                    const __half h1 = __float2half_rn(v1);
                    __half2 hhi = __halves2half2(h0, h1);
                    __half2 hlo = __halves2half2(__float2half_rn(v0 - __half2float(h0)),
                                                 __float2half_rn(v1 - __half2float(h1)));
                    *(__half2*)(Chi + base) = hhi;
                    *(__half2*)(Clo + base) = hlo;
                }
            } else {
                *(float2*)(Cf + (size_t)row * ldc + col) = make_float2(v[0], v[1]);
                *(float2*)(Cf + (size_t)(row + 8) * ldc + col) = make_float2(v[2], v[3]);
            }
        }
    }
}

// ---------------- fp32 -> fp16 hi/lo split (elementwise) ----------------
__global__ __launch_bounds__(256)
void split_kernel(const float* __restrict__ in, __half* __restrict__ hi,
                  __half* __restrict__ lo, int n)
{
    int i = blockIdx.x * 256 + threadIdx.x;
    if (i < n) {
        float x = in[i];
        __half h = __float2half_rn(x);
        hi[i] = h;
        lo[i] = __float2half_rn(x - __half2float(h));
    }
}

// ---------------- W [K,N] fp32 -> transposed [N,K] hi/lo half splits ----------------
__global__ void splitT_kernel(const float* __restrict__ in,
                              __half* __restrict__ hi, __half* __restrict__ lo)
{
    __shared__ float tile[32][33];
    const int x = blockIdx.x * 32 + threadIdx.x;   // N index in input
#pragma unroll
    for (int dy = threadIdx.y; dy < 32; dy += 8)
        tile[dy][threadIdx.x] = in[(size_t)(blockIdx.y * 32 + dy) * DD + x];
    __syncthreads();
    const int k = blockIdx.y * 32 + threadIdx.x;   // K index in output (contiguous)
#pragma unroll
    for (int dy = threadIdx.y; dy < 32; dy += 8) {
        const int n = blockIdx.x * 32 + dy;
        const float v = tile[threadIdx.x][dy];
        const __half h = __float2half_rn(v);
        hi[(size_t)n * DD + k] = h;
        lo[(size_t)n * DD + k] = __float2half_rn(v - __half2float(h));
    }
}

// ---------------- zero vector ----------------
__global__ void zero_kernel(float* __restrict__ p, int n)
{
    int i = blockIdx.x * blockDim.x + threadIdx.x;
    if (i < n) p[i] = 0.0f;
}

// ---------------- iteration 1 (max-tracked LSE) ----------------
__global__ __launch_bounds__(256)
void row_lse_kernel(const float* __restrict__ S, const float* __restrict__ c,
                    float* __restrict__ r)
{
    const size_t i = blockIdx.x;
    const float4* row = (const float4*)(S + i * NR);
    const float4* c4  = (const float4*)c;
    float m = -INFINITY, s = 0.0f;
    for (int j = threadIdx.x; j < NR / 4; j += 256) {
        float4 v  = row[j];
        float4 cc = c4[j];
        lse_add(m, s, v.x - cc.x);
        lse_add(m, s, v.y - cc.y);
        lse_add(m, s, v.z - cc.z);
        lse_add(m, s, v.w - cc.w);
    }
    __shared__ float sm[256], ss[256];
    sm[threadIdx.x] = m; ss[threadIdx.x] = s;
    __syncthreads();
    for (int off = 128; off > 0; off >>= 1) {
        if (threadIdx.x < off)
            lse_merge(sm[threadIdx.x], ss[threadIdx.x],
                      sm[threadIdx.x + off], ss[threadIdx.x + off]);
        __syncthreads();
    }
    if (threadIdx.x == 0) r[i] = sm[0] + logf(ss[0]);
}

__global__ __launch_bounds__(256)
void col_partial_kernel(const float* __restrict__ S, const float* __restrict__ r,
                        float* __restrict__ pm, float* __restrict__ ps)
{
    const int j  = blockIdx.x * 256 + threadIdx.x;
    const int i0 = blockIdx.y * ROWS_PER_CHUNK;
    float m = -INFINITY, s = 0.0f;
#pragma unroll 4
    for (int i = i0; i < i0 + ROWS_PER_CHUNK; ++i) {
        float v = S[(size_t)i * NR + j] - r[i];
        lse_add(m, s, v);
    }
    pm[(size_t)blockIdx.y * NR + j] = m;
    ps[(size_t)blockIdx.y * NR + j] = s;
}

__global__ __launch_bounds__(256)
void col_combine_kernel(const float* __restrict__ pm, const float* __restrict__ ps,
                        float* __restrict__ c)
{
    const int j = blockIdx.x * 256 + threadIdx.x;
    float m = -INFINITY, s = 0.0f;
#pragma unroll 8
    for (int ch = 0; ch < COL_CHUNKS; ++ch)
        lse_merge(m, s, pm[(size_t)ch * NR + j], ps[(size_t)ch * NR + j]);
    c[j] = m + logf(s);
}

// ---------------- fused fast iteration (iterations 2..20) ----------------
// After iteration 1's column update all entries exp(S - r - c) <= 1, so no
// max tracking needed: one streaming pass updates r and emits column partials.
__global__ __launch_bounds__(256)
void sink_iter_kernel(const float* __restrict__ S, float* __restrict__ r,
                      const float* __restrict__ c, float* __restrict__ part)
{
    __shared__ float sc[NR];
    __shared__ float red[8];
    __shared__ float stot;
    const int tid = threadIdx.x;

    for (int j = tid; j < NR / 4; j += 256)
        ((float4*)sc)[j] = ((const float4*)c)[j];
    __syncthreads();

    float4 acc[8];
#pragma unroll
    for (int k = 0; k < 8; ++k) acc[k] = make_float4(0.f, 0.f, 0.f, 0.f);

    const int i0 = blockIdx.x * FRPB;
    for (int ii = 0; ii < FRPB; ++ii) {
        const int i = i0 + ii;
        const float ri = __ldg(&r[i]);
        const float4* row = (const float4*)(S + (size_t)i * NR);
        float4 e[8];
        float s = 0.0f;
#pragma unroll
        for (int k = 0; k < 8; ++k) {
            float4 v  = row[tid + 256 * k];
            float4 cc = ((const float4*)sc)[tid + 256 * k];
            e[k].x = __expf(v.x - cc.x - ri);
            e[k].y = __expf(v.y - cc.y - ri);
            e[k].z = __expf(v.z - cc.z - ri);
            e[k].w = __expf(v.w - cc.w - ri);
            s += (e[k].x + e[k].y) + (e[k].z + e[k].w);
        }
#pragma unroll
        for (int o = 16; o > 0; o >>= 1) s += __shfl_xor_sync(0xffffffffu, s, o);
        if ((tid & 31) == 0) red[tid >> 5] = s;
        __syncthreads();
        if (tid == 0) {
            float t = 0.0f;
#pragma unroll
            for (int w = 0; w < 8; ++w) t += red[w];
            stot = t;
            r[i] = ri + logf(t);
        }
        __syncthreads();
        const float inv = 1.0f / stot;
#pragma unroll
        for (int k = 0; k < 8; ++k) {
            acc[k].x += e[k].x * inv;
            acc[k].y += e[k].y * inv;
            acc[k].z += e[k].z * inv;
            acc[k].w += e[k].w * inv;
        }
    }
    float4* p = (float4*)(part + (size_t)blockIdx.x * NR);
#pragma unroll
    for (int k = 0; k < 8; ++k) p[tid + 256 * k] = acc[k];
}

__global__ __launch_bounds__(256)
void sink_combine_kernel(const float* __restrict__ part, float* __restrict__ c)
{
    const int j = blockIdx.x * 256 + threadIdx.x;
    float s = 0.0f;
#pragma unroll 8
    for (int b = 0; b < FNBLK; ++b) s += part[(size_t)b * NR + j];
    c[j] += logf(s);
}

// ---------------- output: out = exp(S - r_i - c_j) ----------------
__global__ __launch_bounds__(256)
void out_exp_kernel(const float* __restrict__ S, const float* __restrict__ r,
                    const float* __restrict__ c, float* __restrict__ out)
{
    const size_t nq = (size_t)NR * NR / 4;
    const float4* S4 = (const float4*)S;
    const float4* c4 = (const float4*)c;
    float4* o4 = (float4*)out;
    size_t idx = (size_t)blockIdx.x * blockDim.x + threadIdx.x;
    const size_t stride = (size_t)gridDim.x * blockDim.x;
    for (; idx < nq; idx += stride) {
        size_t i  = idx / (NR / 4);
        size_t jq = idx % (NR / 4);
        float ri = r[i];
        float4 cc = c4[jq];
        float4 v = S4[idx];
        float4 o;
        o.x = __expf(v.x - ri - cc.x);
        o.y = __expf(v.y - ri - cc.y);
        o.z = __expf(v.z - ri - cc.z);
        o.w = __expf(v.w - ri - cc.w);
        o4[idx] = o;
    }
}

// ---------------- launch ----------------
extern "C" void kernel_launch(void* const* d_in, const int* in_sizes, int n_in,
                              void* d_out, int out_size)
{
    const float* emb_a = (const float*)d_in[0];
    const float* emb_b = (const float*)d_in[1];
    const float* W1    = (const float*)d_in[2];
    const float* b1    = (const float*)d_in[3];
    const float* W2    = (const float*)d_in[4];
    const float* b2    = (const float*)d_in[5];
    float* out = (float*)d_out;

    float *scores, *r, *c, *pm, *ps, *part;
    __half *x_hi, *x_lo, *h_hi, *h_lo, *a_hi, *a_lo, *b_hi, *b_lo;
    __half *w1_hi, *w1_lo, *w2_hi, *w2_lo;
    cudaGetSymbolAddress((void**)&scores, g_scores);
    cudaGetSymbolAddress((void**)&x_hi, g_x_hi);
    cudaGetSymbolAddress((void**)&x_lo, g_x_lo);
    cudaGetSymbolAddress((void**)&h_hi, g_h_hi);
    cudaGetSymbolAddress((void**)&h_lo, g_h_lo);
    cudaGetSymbolAddress((void**)&a_hi, g_a_hi);
    cudaGetSymbolAddress((void**)&a_lo, g_a_lo);
    cudaGetSymbolAddress((void**)&b_hi, g_b_hi);
    cudaGetSymbolAddress((void**)&b_lo, g_b_lo);
    cudaGetSymbolAddress((void**)&w1_hi, g_w1_hi);
    cudaGetSymbolAddress((void**)&w1_lo, g_w1_lo);
    cudaGetSymbolAddress((void**)&w2_hi, g_w2_hi);
    cudaGetSymbolAddress((void**)&w2_lo, g_w2_lo);
    cudaGetSymbolAddress((void**)&r,  g_r);
    cudaGetSymbolAddress((void**)&c,  g_c);
    cudaGetSymbolAddress((void**)&pm, g_pm);
    cudaGetSymbolAddress((void**)&ps, g_ps);
    cudaGetSymbolAddress((void**)&part, g_part);

    cudaFuncSetAttribute(hmma_kernel<1, 1>,
                         cudaFuncAttributeMaxDynamicSharedMemorySize, SMEM_HMMA);
    cudaFuncSetAttribute(hmma_kernel<0, 1>,
                         cudaFuncAttributeMaxDynamicSharedMemorySize, SMEM_HMMA);
    cudaFuncSetAttribute(hmma_kernel<0, 0>,
                         cudaFuncAttributeMaxDynamicSharedMemorySize, SMEM_HMMA);

    const int nel = NR * DD;
    const dim3 gProj(DD / 128, NR / 128);     // (8, 64)
    const dim3 gScore(NR / 128, NR / 128);    // (64, 64)

    // weight split + transpose to [N, K]
    splitT_kernel<<<dim3(32, 32), dim3(32, 8)>>>(W1, w1_hi, w1_lo);
    splitT_kernel<<<dim3(32, 32), dim3(32, 8)>>>(W2, w2_hi, w2_lo);

    // branch a: emb_a -> gelu(xW1+b1) -> (hW2+b2) as splits
    split_kernel<<<nel / 256, 256>>>(emb_a, x_hi, x_lo, nel);
    hmma_kernel<1, 1><<<gProj, 256, SMEM_HMMA>>>(x_hi, x_lo, w1_hi, w1_lo, b1,
                                                 nullptr, h_hi, h_lo, DD, DD, 1.0f);
    hmma_kernel<0, 1><<<gProj, 256, SMEM_HMMA>>>(h_hi, h_lo, w2_hi, w2_lo, b2,
                                                 nullptr, a_hi, a_lo, DD, DD, 1.0f);
    // branch b
    split_kernel<<<nel / 256, 256>>>(emb_b, x_hi, x_lo, nel);
    hmma_kernel<1, 1><<<gProj, 256, SMEM_HMMA>>>(x_hi, x_lo, w1_hi, w1_lo, b1,
                                                 nullptr, h_hi, h_lo, DD, DD, 1.0f);
    hmma_kernel<0, 1><<<gProj, 256, SMEM_HMMA>>>(h_hi, h_lo, w2_hi, w2_lo, b2,
                                                 nullptr, b_hi, b_lo, DD, DD, 1.0f);

    // scores = 20 * a @ b^T
    hmma_kernel<0, 0><<<gScore, 256, SMEM_HMMA>>>(a_hi, a_lo, b_hi, b_lo, nullptr,
                                                  scores, nullptr, nullptr, NR, DD,
                                                  INV_TEMP);

    // Sinkhorn iteration 1 (max-tracked)
    zero_kernel<<<NR / 256, 256>>>(c, NR);
    row_lse_kernel<<<NR, 256>>>(scores, c, r);
    col_partial_kernel<<<dim3(NR / 256, COL_CHUNKS), 256>>>(scores, r, pm, ps);
    col_combine_kernel<<<NR / 256, 256>>>(pm, ps, c);

    // iterations 2..20: fused single-pass
    for (int it = 1; it < ITERS; ++it) {
        sink_iter_kernel<<<FNBLK, 256>>>(scores, r, c, part);
        sink_combine_kernel<<<NR / 256, 256>>>(part, c);
    }

    // final output
    out_exp_kernel<<<2048, 256>>>(scores, r, c, out);
}

// round 7
// speedup vs baseline: 1.4127x; 1.4127x over previous
#include <cuda_runtime.h>
#include <cuda_fp16.h>
#include <math.h>
#include <stdint.h>

// Problem constants
#define NR 8192
#define DD 1024
#define ITERS 20
#define INV_TEMP 20.0f

// iteration-1 column pass chunking
#define COL_CHUNKS 64
#define ROWS_PER_CHUNK (NR / COL_CHUNKS)

// fast fused Sinkhorn iteration
#define FRPB 16
#define FNBLK (NR / FRPB)   // 512

// HMMA tiling: BM=128, BN=128, BK=64, 8 warps (2 M x 4 N), warp tile 64x32
#define HBK 64
#define ROWB 144                      // padded row stride in bytes (64 halfs + 16 pad)
#define TILEB (128 * ROWB)            // 18432 B per operand tile
#define BUFB (4 * TILEB)              // 73728 B per stage (Ahi,Alo,Bhi,Blo)
#define SMEM_HMMA (2 * BUFB)          // 147456 B double buffered

// ---------------- device scratch (static, no allocation) ----------------
__device__ float g_scores[(size_t)NR * NR];   // 256 MB
__device__ __half g_x_hi[(size_t)NR * DD];
__device__ __half g_x_lo[(size_t)NR * DD];
__device__ __half g_h_hi[(size_t)NR * DD];
__device__ __half g_h_lo[(size_t)NR * DD];
__device__ __half g_a_hi[(size_t)NR * DD];
__device__ __half g_a_lo[(size_t)NR * DD];
__device__ __half g_b_hi[(size_t)NR * DD];
__device__ __half g_b_lo[(size_t)NR * DD];
__device__ __half g_w1_hi[(size_t)DD * DD];
__device__ __half g_w1_lo[(size_t)DD * DD];
__device__ __half g_w2_hi[(size_t)DD * DD];
__device__ __half g_w2_lo[(size_t)DD * DD];
__device__ float g_r[NR];
__device__ float g_c[NR];
__device__ float g_pm[(size_t)COL_CHUNKS * NR];
__device__ float g_ps[(size_t)COL_CHUNKS * NR];
__device__ float g_part[(size_t)FNBLK * NR];  // 16 MB

// ---------------- small helpers ----------------
__device__ __forceinline__ uint32_t smem_to_u32(const void* smem_ptr) {
    uint32_t addr;
    asm("{ .reg .u64 tmp; cvta.to.shared.u64 tmp, %1; cvt.u32.u64 %0, tmp; }"
        : "=r"(addr) : "l"(smem_ptr));
    return addr;
}
__device__ __forceinline__ void cp16(uint32_t saddr, const void* g) {
    asm volatile("cp.async.cg.shared.global [%0], [%1], 16;" :: "r"(saddr), "l"(g));
}
__device__ __forceinline__ void cp_commit() {
    asm volatile("cp.async.commit_group;");
}
template <int N> __device__ __forceinline__ void cp_wait() {
    asm volatile("cp.async.wait_group %0;" :: "n"(N));
}
__device__ __forceinline__ void ldsm_x4(uint32_t* r, uint32_t addr) {
    asm volatile("ldmatrix.sync.aligned.m8n8.x4.shared.b16 {%0,%1,%2,%3}, [%4];"
                 : "=r"(r[0]), "=r"(r[1]), "=r"(r[2]), "=r"(r[3]) : "r"(addr));
}
__device__ __forceinline__ void ldsm_x2(uint32_t* r, uint32_t addr) {
    asm volatile("ldmatrix.sync.aligned.m8n8.x2.shared.b16 {%0,%1}, [%2];"
                 : "=r"(r[0]), "=r"(r[1]) : "r"(addr));
}
__device__ __forceinline__ void mma16816(float* c, const uint32_t* a, const uint32_t* b) {
    asm volatile(
        "mma.sync.aligned.m16n8k16.row.col.f32.f16.f16.f32 "
        "{%0,%1,%2,%3}, {%4,%5,%6,%7}, {%8,%9}, {%0,%1,%2,%3};"
        : "+f"(c[0]), "+f"(c[1]), "+f"(c[2]), "+f"(c[3])
        : "r"(a[0]), "r"(a[1]), "r"(a[2]), "r"(a[3]), "r"(b[0]), "r"(b[1]));
}
__device__ __forceinline__ float gelu_exact(float x) {
    return 0.5f * x * (1.0f + erff(x * 0.70710678118654752440f));
}
__device__ __forceinline__ void lse_add(float& m, float& s, float v) {
    if (v <= m) { s += __expf(v - m); }
    else        { s = s * __expf(m - v) + 1.0f; m = v; }
}
__device__ __forceinline__ void lse_merge(float& m1, float& s1, float m2, float s2) {
    if (m2 == -INFINITY) return;
    if (m1 == -INFINITY) { m1 = m2; s1 = s2; return; }
    if (m2 <= m1) { s1 += s2 * __expf(m2 - m1); }
    else { s1 = s1 * __expf(m1 - m2) + s2; m1 = m2; }
}

// ---------------- HMMA GEMM: C = epilogue(scale*(A @ B^T) [+ bias]) ----------------
// A: [M, K] hi/lo half splits (row-major, K contiguous)
// B: [N, K] hi/lo half splits (row-major, K contiguous)
// 2-split product: hh + hl + lh (fp32 accumulate)
// 1 CTA/SM (reg-bound); BK=64 amortizes barrier + ldsm bubbles over 192
// HMMA per warp per tile.
template <int ACT, int OUT_SPLIT>
__global__ __launch_bounds__(256)
void hmma_kernel(const __half* __restrict__ Ah, const __half* __restrict__ Al,
                 const __half* __restrict__ Bh, const __half* __restrict__ Bl,
                 const float* __restrict__ bias,
                 float* __restrict__ Cf, __half* __restrict__ Chi, __half* __restrict__ Clo,
                 int ldc, int Kdim, float scale)
{
    extern __shared__ __align__(16) char smem[];
    const uint32_t sbase = smem_to_u32(smem);
    const int tid  = threadIdx.x;
    const int warp = tid >> 5;
    const int lane = tid & 31;
    const int wm = warp >> 2;       // 0..1 (64-row slab)
    const int wn = warp & 3;        // 0..3 (32-col slab)

    const int m0 = blockIdx.y * 128;
    const int n0 = blockIdx.x * 128;

    const __half* gsrc0 = Ah + (size_t)m0 * Kdim;
    const __half* gsrc1 = Al + (size_t)m0 * Kdim;
    const __half* gsrc2 = Bh + (size_t)n0 * Kdim;
    const __half* gsrc3 = Bl + (size_t)n0 * Kdim;

    float acc[4][4][4];
#pragma unroll
    for (int i = 0; i < 4; i++)
#pragma unroll
        for (int j = 0; j < 4; j++)
#pragma unroll
            for (int k = 0; k < 4; k++) acc[i][j][k] = 0.0f;

    const int nTiles = Kdim / HBK;

    // ---- async tile loader: 16 x 16B chunks per thread per stage ----
    // Each operand tile: 128 rows x 128B = 1024 16B-chunks = 4 rounds of 256 thr.
    auto issue = [&](int buf, int kt) {
#pragma unroll
        for (int j = 0; j < 16; j++) {
            const int tile = j >> 2;
            const int qq = (j & 3) * 256 + tid;
            const int r = qq >> 3;          // row 0..127
            const int cch = qq & 7;         // 16B chunk within 128B row
            const __half* g;
            if      (tile == 0) g = gsrc0 + (size_t)r * Kdim + kt + cch * 8;
            else if (tile == 1) g = gsrc1 + (size_t)r * Kdim + kt + cch * 8;
            else if (tile == 2) g = gsrc2 + (size_t)r * Kdim + kt + cch * 8;
            else                g = gsrc3 + (size_t)r * Kdim + kt + cch * 8;
            cp16(sbase + buf * BUFB + tile * TILEB + r * ROWB + cch * 16, g);
        }
        cp_commit();
    };

    issue(0, 0);

    // per-lane ldmatrix address components (loop invariant)
    const int arow = wm * 64 + (lane & 15);
    const int akof = (lane >> 4) * 8;
    const int brow = wn * 32 + (lane & 7);
    const int bkof = ((lane >> 3) & 1) * 8;

    for (int t = 0; t < nTiles; ++t) {
        if (t + 1 < nTiles) {
            issue((t + 1) & 1, (t + 1) * HBK);
            cp_wait<1>();
        } else {
            cp_wait<0>();
        }
        __syncthreads();

        const uint32_t bufb = sbase + (t & 1) * BUFB;
        const uint32_t aBhi = bufb;
        const uint32_t aBlo = bufb + TILEB;
        const uint32_t bBhi = bufb + 2 * TILEB;
        const uint32_t bBlo = bufb + 3 * TILEB;

#pragma unroll
        for (int ks = 0; ks < HBK; ks += 16) {
            uint32_t bh[4][2];
#pragma unroll
            for (int bn = 0; bn < 4; bn++) {
                const uint32_t off = (uint32_t)(brow + bn * 8) * ROWB + (ks + bkof) * 2;
                ldsm_x2(bh[bn], bBhi + off);
            }
            uint32_t af[4][4];
#pragma unroll
            for (int am = 0; am < 4; am++) {
                const uint32_t off = (uint32_t)(arow + am * 16) * ROWB + (ks + akof) * 2;
                ldsm_x4(af[am], aBhi + off);
            }
            // hi * hi
#pragma unroll
            for (int am = 0; am < 4; am++)
#pragma unroll
                for (int bn = 0; bn < 4; bn++)
                    mma16816(acc[am][bn], af[am], bh[bn]);
            // hi * lo
            {
                uint32_t bl[4][2];
#pragma unroll
                for (int bn = 0; bn < 4; bn++) {
                    const uint32_t off = (uint32_t)(brow + bn * 8) * ROWB + (ks + bkof) * 2;
                    ldsm_x2(bl[bn], bBlo + off);
                }
#pragma unroll
                for (int am = 0; am < 4; am++)
#pragma unroll
                    for (int bn = 0; bn < 4; bn++)
                        mma16816(acc[am][bn], af[am], bl[bn]);
            }
            // lo * hi (reuse af registers)
#pragma unroll
            for (int am = 0; am < 4; am++) {
                const uint32_t off = (uint32_t)(arow + am * 16) * ROWB + (ks + akof) * 2;
                ldsm_x4(af[am], aBlo + off);
            }
#pragma unroll
            for (int am = 0; am < 4; am++)
#pragma unroll
                for (int bn = 0; bn < 4; bn++)
                    mma16816(acc[am][bn], af[am], bh[bn]);
        }
        __syncthreads();
    }

    // ---- epilogue ----
#pragma unroll
    for (int am = 0; am < 4; am++) {
#pragma unroll
        for (int bn = 0; bn < 4; bn++) {
            const int row = m0 + wm * 64 + am * 16 + (lane >> 2);
            const int col = n0 + wn * 32 + bn * 8 + (lane & 3) * 2;
            float v[4];
#pragma unroll
            for (int k = 0; k < 4; k++) v[k] = acc[am][bn][k] * scale;
            if (bias) {
                const float bx = bias[col], by = bias[col + 1];
                v[0] += bx; v[1] += by; v[2] += bx; v[3] += by;
            }
            if (ACT == 1) {
#pragma unroll
                for (int k = 0; k < 4; k++) v[k] = gelu_exact(v[k]);
            }
            if (OUT_SPLIT == 1) {
#pragma unroll
                for (int half_row = 0; half_row < 2; half_row++) {
                    const size_t base = (size_t)(row + half_row * 8) * ldc + col;
                    const float v0 = v[half_row * 2], v1 = v[half_row * 2 + 1];
                    const __half h0 = __float2half_rn(v0);
                    const __half h1 = __float2half_rn(v1);
                    __half2 hhi = __halves2half2(h0, h1);
                    __half2 hlo = __halves2half2(__float2half_rn(v0 - __half2float(h0)),
                                                 __float2half_rn(v1 - __half2float(h1)));
                    *(__half2*)(Chi + base) = hhi;
                    *(__half2*)(Clo + base) = hlo;
                }
            } else {
                *(float2*)(Cf + (size_t)row * ldc + col) = make_float2(v[0], v[1]);
                *(float2*)(Cf + (size_t)(row + 8) * ldc + col) = make_float2(v[2], v[3]);
            }
        }
    }
}

// ---------------- fp32 -> fp16 hi/lo split (elementwise) ----------------
__global__ __launch_bounds__(256)
void split_kernel(const float* __restrict__ in, __half* __restrict__ hi,
                  __half* __restrict__ lo, int n)
{
    int i = blockIdx.x * 256 + threadIdx.x;
    if (i < n) {
        float x = in[i];
        __half h = __float2half_rn(x);
        hi[i] = h;
        lo[i] = __float2half_rn(x - __half2float(h));
    }
}

// ---------------- W [K,N] fp32 -> transposed [N,K] hi/lo half splits ----------------
__global__ void splitT_kernel(const float* __restrict__ in,
                              __half* __restrict__ hi, __half* __restrict__ lo)
{
    __shared__ float tile[32][33];
    const int x = blockIdx.x * 32 + threadIdx.x;   // N index in input
#pragma unroll
    for (int dy = threadIdx.y; dy < 32; dy += 8)
        tile[dy][threadIdx.x] = in[(size_t)(blockIdx.y * 32 + dy) * DD + x];
    __syncthreads();
    const int k = blockIdx.y * 32 + threadIdx.x;   // K index in output (contiguous)
#pragma unroll
    for (int dy = threadIdx.y; dy < 32; dy += 8) {
        const int n = blockIdx.x * 32 + dy;
        const float v = tile[threadIdx.x][dy];
        const __half h = __float2half_rn(v);
        hi[(size_t)n * DD + k] = h;
        lo[(size_t)n * DD + k] = __float2half_rn(v - __half2float(h));
    }
}

// ---------------- zero vector ----------------
__global__ void zero_kernel(float* __restrict__ p, int n)
{
    int i = blockIdx.x * blockDim.x + threadIdx.x;
    if (i < n) p[i] = 0.0f;
}

// ---------------- iteration 1 (max-tracked LSE) ----------------
__global__ __launch_bounds__(256)
void row_lse_kernel(const float* __restrict__ S, const float* __restrict__ c,
                    float* __restrict__ r)
{
    const size_t i = blockIdx.x;
    const float4* row = (const float4*)(S + i * NR);
    const float4* c4  = (const float4*)c;
    float m = -INFINITY, s = 0.0f;
    for (int j = threadIdx.x; j < NR / 4; j += 256) {
        float4 v  = row[j];
        float4 cc = c4[j];
        lse_add(m, s, v.x - cc.x);
        lse_add(m, s, v.y - cc.y);
        lse_add(m, s, v.z - cc.z);
        lse_add(m, s, v.w - cc.w);
    }
    __shared__ float sm[256], ss[256];
    sm[threadIdx.x] = m; ss[threadIdx.x] = s;
    __syncthreads();
    for (int off = 128; off > 0; off >>= 1) {
        if (threadIdx.x < off)
            lse_merge(sm[threadIdx.x], ss[threadIdx.x],
                      sm[threadIdx.x + off], ss[threadIdx.x + off]);
        __syncthreads();
    }
    if (threadIdx.x == 0) r[i] = sm[0] + logf(ss[0]);
}

__global__ __launch_bounds__(256)
void col_partial_kernel(const float* __restrict__ S, const float* __restrict__ r,
                        float* __restrict__ pm, float* __restrict__ ps)
{
    const int j  = blockIdx.x * 256 + threadIdx.x;
    const int i0 = blockIdx.y * ROWS_PER_CHUNK;
    float m = -INFINITY, s = 0.0f;
#pragma unroll 4
    for (int i = i0; i < i0 + ROWS_PER_CHUNK; ++i) {
        float v = S[(size_t)i * NR + j] - r[i];
        lse_add(m, s, v);
    }
    pm[(size_t)blockIdx.y * NR + j] = m;
    ps[(size_t)blockIdx.y * NR + j] = s;
}

__global__ __launch_bounds__(256)
void col_combine_kernel(const float* __restrict__ pm, const float* __restrict__ ps,
                        float* __restrict__ c)
{
    const int j = blockIdx.x * 256 + threadIdx.x;
    float m = -INFINITY, s = 0.0f;
#pragma unroll 8
    for (int ch = 0; ch < COL_CHUNKS; ++ch)
        lse_merge(m, s, pm[(size_t)ch * NR + j], ps[(size_t)ch * NR + j]);
    c[j] = m + logf(s);
}

// ---------------- fused fast iteration (iterations 2..20) ----------------
// After iteration 1's column update all entries exp(S - r - c) <= 1, so no
// max tracking needed: one streaming pass updates r and emits column partials.
__global__ __launch_bounds__(256)
void sink_iter_kernel(const float* __restrict__ S, float* __restrict__ r,
                      const float* __restrict__ c, float* __restrict__ part)
{
    __shared__ float sc[NR];
    __shared__ float red[8];
    __shared__ float stot;
    const int tid = threadIdx.x;

    for (int j = tid; j < NR / 4; j += 256)
        ((float4*)sc)[j] = ((const float4*)c)[j];
    __syncthreads();

    float4 acc[8];
#pragma unroll
    for (int k = 0; k < 8; ++k) acc[k] = make_float4(0.f, 0.f, 0.f, 0.f);

    const int i0 = blockIdx.x * FRPB;
    for (int ii = 0; ii < FRPB; ++ii) {
        const int i = i0 + ii;
        const float ri = __ldg(&r[i]);
        const float4* row = (const float4*)(S + (size_t)i * NR);
        float4 e[8];
        float s = 0.0f;
#pragma unroll
        for (int k = 0; k < 8; ++k) {
            float4 v  = row[tid + 256 * k];
            float4 cc = ((const float4*)sc)[tid + 256 * k];
            e[k].x = __expf(v.x - cc.x - ri);
            e[k].y = __expf(v.y - cc.y - ri);
            e[k].z = __expf(v.z - cc.z - ri);
            e[k].w = __expf(v.w - cc.w - ri);
            s += (e[k].x + e[k].y) + (e[k].z + e[k].w);
        }
#pragma unroll
        for (int o = 16; o > 0; o >>= 1) s += __shfl_xor_sync(0xffffffffu, s, o);
        if ((tid & 31) == 0) red[tid >> 5] = s;
        __syncthreads();
        if (tid == 0) {
            float t = 0.0f;
#pragma unroll
            for (int w = 0; w < 8; ++w) t += red[w];
            stot = t;
            r[i] = ri + logf(t);
        }
        __syncthreads();
        const float inv = 1.0f / stot;
#pragma unroll
        for (int k = 0; k < 8; ++k) {
            acc[k].x += e[k].x * inv;
            acc[k].y += e[k].y * inv;
            acc[k].z += e[k].z * inv;
            acc[k].w += e[k].w * inv;
        }
    }
    float4* p = (float4*)(part + (size_t)blockIdx.x * NR);
#pragma unroll
    for (int k = 0; k < 8; ++k) p[tid + 256 * k] = acc[k];
}

__global__ __launch_bounds__(256)
void sink_combine_kernel(const float* __restrict__ part, float* __restrict__ c)
{
    const int j = blockIdx.x * 256 + threadIdx.x;
    float s = 0.0f;
#pragma unroll 8
    for (int b = 0; b < FNBLK; ++b) s += part[(size_t)b * NR + j];
    c[j] += logf(s);
}

// ---------------- output: out = exp(S - r_i - c_j) ----------------
__global__ __launch_bounds__(256)
void out_exp_kernel(const float* __restrict__ S, const float* __restrict__ r,
                    const float* __restrict__ c, float* __restrict__ out)
{
    const size_t nq = (size_t)NR * NR / 4;
    const float4* S4 = (const float4*)S;
    const float4* c4 = (const float4*)c;
    float4* o4 = (float4*)out;
    size_t idx = (size_t)blockIdx.x * blockDim.x + threadIdx.x;
    const size_t stride = (size_t)gridDim.x * blockDim.x;
    for (; idx < nq; idx += stride) {
        size_t i  = idx / (NR / 4);
        size_t jq = idx % (NR / 4);
        float ri = r[i];
        float4 cc = c4[jq];
        float4 v = S4[idx];
        float4 o;
        o.x = __expf(v.x - ri - cc.x);
        o.y = __expf(v.y - ri - cc.y);
        o.z = __expf(v.z - ri - cc.z);
        o.w = __expf(v.w - ri - cc.w);
        o4[idx] = o;
    }
}

// ---------------- launch ----------------
extern "C" void kernel_launch(void* const* d_in, const int* in_sizes, int n_in,
                              void* d_out, int out_size)
{
    const float* emb_a = (const float*)d_in[0];
    const float* emb_b = (const float*)d_in[1];
    const float* W1    = (const float*)d_in[2];
    const float* b1    = (const float*)d_in[3];
    const float* W2    = (const float*)d_in[4];
    const float* b2    = (const float*)d_in[5];
    float* out = (float*)d_out;

    float *scores, *r, *c, *pm, *ps, *part;
    __half *x_hi, *x_lo, *h_hi, *h_lo, *a_hi, *a_lo, *b_hi, *b_lo;
    __half *w1_hi, *w1_lo, *w2_hi, *w2_lo;
    cudaGetSymbolAddress((void**)&scores, g_scores);
    cudaGetSymbolAddress((void**)&x_hi, g_x_hi);
    cudaGetSymbolAddress((void**)&x_lo, g_x_lo);
    cudaGetSymbolAddress((void**)&h_hi, g_h_hi);
    cudaGetSymbolAddress((void**)&h_lo, g_h_lo);
    cudaGetSymbolAddress((void**)&a_hi, g_a_hi);
    cudaGetSymbolAddress((void**)&a_lo, g_a_lo);
    cudaGetSymbolAddress((void**)&b_hi, g_b_hi);
    cudaGetSymbolAddress((void**)&b_lo, g_b_lo);
    cudaGetSymbolAddress((void**)&w1_hi, g_w1_hi);
    cudaGetSymbolAddress((void**)&w1_lo, g_w1_lo);
    cudaGetSymbolAddress((void**)&w2_hi, g_w2_hi);
    cudaGetSymbolAddress((void**)&w2_lo, g_w2_lo);
    cudaGetSymbolAddress((void**)&r,  g_r);
    cudaGetSymbolAddress((void**)&c,  g_c);
    cudaGetSymbolAddress((void**)&pm, g_pm);
    cudaGetSymbolAddress((void**)&ps, g_ps);
    cudaGetSymbolAddress((void**)&part, g_part);

    cudaFuncSetAttribute(hmma_kernel<1, 1>,
                         cudaFuncAttributeMaxDynamicSharedMemorySize, SMEM_HMMA);
    cudaFuncSetAttribute(hmma_kernel<0, 1>,
                         cudaFuncAttributeMaxDynamicSharedMemorySize, SMEM_HMMA);
    cudaFuncSetAttribute(hmma_kernel<0, 0>,
                         cudaFuncAttributeMaxDynamicSharedMemorySize, SMEM_HMMA);

    const int nel = NR * DD;
    const dim3 gProj(DD / 128, NR / 128);     // (8, 64)
    const dim3 gScore(NR / 128, NR / 128);    // (64, 64)

    // weight split + transpose to [N, K]
    splitT_kernel<<<dim3(32, 32), dim3(32, 8)>>>(W1, w1_hi, w1_lo);
    splitT_kernel<<<dim3(32, 32), dim3(32, 8)>>>(W2, w2_hi, w2_lo);

    // branch a: emb_a -> gelu(xW1+b1) -> (hW2+b2) as splits
    split_kernel<<<nel / 256, 256>>>(emb_a, x_hi, x_lo, nel);
    hmma_kernel<1, 1><<<gProj, 256, SMEM_HMMA>>>(x_hi, x_lo, w1_hi, w1_lo, b1,
                                                 nullptr, h_hi, h_lo, DD, DD, 1.0f);
    hmma_kernel<0, 1><<<gProj, 256, SMEM_HMMA>>>(h_hi, h_lo, w2_hi, w2_lo, b2,
                                                 nullptr, a_hi, a_lo, DD, DD, 1.0f);
    // branch b
    split_kernel<<<nel / 256, 256>>>(emb_b, x_hi, x_lo, nel);
    hmma_kernel<1, 1><<<gProj, 256, SMEM_HMMA>>>(x_hi, x_lo, w1_hi, w1_lo, b1,
                                                 nullptr, h_hi, h_lo, DD, DD, 1.0f);
    hmma_kernel<0, 1><<<gProj, 256, SMEM_HMMA>>>(h_hi, h_lo, w2_hi, w2_lo, b2,
                                                 nullptr, b_hi, b_lo, DD, DD, 1.0f);

    // scores = 20 * a @ b^T
    hmma_kernel<0, 0><<<gScore, 256, SMEM_HMMA>>>(a_hi, a_lo, b_hi, b_lo, nullptr,
                                                  scores, nullptr, nullptr, NR, DD,
                                                  INV_TEMP);

    // Sinkhorn iteration 1 (max-tracked)
    zero_kernel<<<NR / 256, 256>>>(c, NR);
    row_lse_kernel<<<NR, 256>>>(scores, c, r);
    col_partial_kernel<<<dim3(NR / 256, COL_CHUNKS), 256>>>(scores, r, pm, ps);
    col_combine_kernel<<<NR / 256, 256>>>(pm, ps, c);

    // iterations 2..20: fused single-pass
    for (int it = 1; it < ITERS; ++it) {
        sink_iter_kernel<<<FNBLK, 256>>>(scores, r, c, part);
        sink_combine_kernel<<<NR / 256, 256>>>(part, c);
    }

    // final output
    out_exp_kernel<<<2048, 256>>>(scores, r, c, out);
}

// round 9
// speedup vs baseline: 1.5481x; 1.0958x over previous
#include <cuda_runtime.h>
#include <cuda_fp16.h>
#include <math.h>
#include <stdint.h>

// Problem constants
#define NR 8192
#define DD 1024
#define ITERS 20
#define INV_TEMP 20.0f

// fused Sinkhorn iteration blocking
#define FRPB 16
#define FNBLK (NR / FRPB)   // 512

// HMMA tiling: BM=128, BN=128, BK=64, 8 warps (2 M x 4 N), warp tile 64x32
#define HBK 64
#define ROWB 144                      // padded row stride in bytes (64 halfs + 16 pad)
#define TILEB (128 * ROWB)            // 18432 B per operand tile
#define BUFB (4 * TILEB)              // 73728 B per stage (Ahi,Alo,Bhi,Blo)
#define SMEM_HMMA (2 * BUFB)          // 147456 B double buffered

// ---------------- device scratch (static, no allocation) ----------------
__device__ float g_scores[(size_t)NR * NR];   // 256 MB
__device__ __half g_x_hi[(size_t)NR * DD];
__device__ __half g_x_lo[(size_t)NR * DD];
__device__ __half g_h_hi[(size_t)NR * DD];
__device__ __half g_h_lo[(size_t)NR * DD];
__device__ __half g_a_hi[(size_t)NR * DD];
__device__ __half g_a_lo[(size_t)NR * DD];
__device__ __half g_b_hi[(size_t)NR * DD];
__device__ __half g_b_lo[(size_t)NR * DD];
__device__ __half g_w1_hi[(size_t)DD * DD];
__device__ __half g_w1_lo[(size_t)DD * DD];
__device__ __half g_w2_hi[(size_t)DD * DD];
__device__ __half g_w2_lo[(size_t)DD * DD];
__device__ float g_r[NR];
__device__ float g_c[NR];
__device__ float g_pm[(size_t)FNBLK * NR];    // 16 MB (iter-1 col LSE max)
__device__ float g_ps[(size_t)FNBLK * NR];    // 16 MB (iter-1 col LSE sum / later plain sums)

// ---------------- small helpers ----------------
__device__ __forceinline__ uint32_t smem_to_u32(const void* smem_ptr) {
    uint32_t addr;
    asm("{ .reg .u64 tmp; cvta.to.shared.u64 tmp, %1; cvt.u32.u64 %0, tmp; }"
        : "=r"(addr) : "l"(smem_ptr));
    return addr;
}
__device__ __forceinline__ void cp16(uint32_t saddr, const void* g) {
    asm volatile("cp.async.cg.shared.global [%0], [%1], 16;" :: "r"(saddr), "l"(g));
}
__device__ __forceinline__ void cp_commit() {
    asm volatile("cp.async.commit_group;");
}
template <int N> __device__ __forceinline__ void cp_wait() {
    asm volatile("cp.async.wait_group %0;" :: "n"(N));
}
__device__ __forceinline__ void ldsm_x4(uint32_t* r, uint32_t addr) {
    asm volatile("ldmatrix.sync.aligned.m8n8.x4.shared.b16 {%0,%1,%2,%3}, [%4];"
                 : "=r"(r[0]), "=r"(r[1]), "=r"(r[2]), "=r"(r[3]) : "r"(addr));
}
__device__ __forceinline__ void ldsm_x2(uint32_t* r, uint32_t addr) {
    asm volatile("ldmatrix.sync.aligned.m8n8.x2.shared.b16 {%0,%1}, [%2];"
                 : "=r"(r[0]), "=r"(r[1]) : "r"(addr));
}
__device__ __forceinline__ void mma16816(float* c, const uint32_t* a, const uint32_t* b) {
    asm volatile(
        "mma.sync.aligned.m16n8k16.row.col.f32.f16.f16.f32 "
        "{%0,%1,%2,%3}, {%4,%5,%6,%7}, {%8,%9}, {%0,%1,%2,%3};"
        : "+f"(c[0]), "+f"(c[1]), "+f"(c[2]), "+f"(c[3])
        : "r"(a[0]), "r"(a[1]), "r"(a[2]), "r"(a[3]), "r"(b[0]), "r"(b[1]));
}
__device__ __forceinline__ float gelu_exact(float x) {
    return 0.5f * x * (1.0f + erff(x * 0.70710678118654752440f));
}
__device__ __forceinline__ void lse_add(float& m, float& s, float v) {
    if (v <= m) { s += __expf(v - m); }
    else        { s = s * __expf(m - v) + 1.0f; m = v; }
}
__device__ __forceinline__ void lse_merge(float& m1, float& s1, float m2, float s2) {
    if (m2 == -INFINITY) return;
    if (m1 == -INFINITY) { m1 = m2; s1 = s2; return; }
    if (m2 <= m1) { s1 += s2 * __expf(m2 - m1); }
    else { s1 = s1 * __expf(m1 - m2) + s2; m1 = m2; }
}

// ---------------- HMMA GEMM: C = epilogue(scale*(A @ B^T) [+ bias]) ----------------
// A: [M, K] hi/lo half splits; B: [N, K] hi/lo half splits (row-major, K contig)
// 2-split product: hh + hl + lh (fp32 accumulate).
// Fragment pipeline: ah/bh double-buffered across K-groups; next group's ldsm
// issued between hh and hl MMA blocks so LDSM latency hides under MMA bursts.
template <int ACT, int OUT_SPLIT>
__global__ __launch_bounds__(256)
void hmma_kernel(const __half* __restrict__ Ah, const __half* __restrict__ Al,
                 const __half* __restrict__ Bh, const __half* __restrict__ Bl,
                 const float* __restrict__ bias,
                 float* __restrict__ Cf, __half* __restrict__ Chi, __half* __restrict__ Clo,
                 int ldc, int Kdim, float scale)
{
    extern __shared__ __align__(16) char smem[];
    const uint32_t sbase = smem_to_u32(smem);
    const int tid  = threadIdx.x;
    const int warp = tid >> 5;
    const int lane = tid & 31;
    const int wm = warp >> 2;       // 0..1 (64-row slab)
    const int wn = warp & 3;        // 0..3 (32-col slab)

    const int m0 = blockIdx.y * 128;
    const int n0 = blockIdx.x * 128;

    const __half* gsrc0 = Ah + (size_t)m0 * Kdim;
    const __half* gsrc1 = Al + (size_t)m0 * Kdim;
    const __half* gsrc2 = Bh + (size_t)n0 * Kdim;
    const __half* gsrc3 = Bl + (size_t)n0 * Kdim;

    float acc[4][4][4];
#pragma unroll
    for (int i = 0; i < 4; i++)
#pragma unroll
        for (int j = 0; j < 4; j++)
#pragma unroll
            for (int k = 0; k < 4; k++) acc[i][j][k] = 0.0f;

    const int nTiles = Kdim / HBK;

    // ---- async tile loader: 16 x 16B chunks per thread per stage ----
    auto issue = [&](int buf, int kt) {
#pragma unroll
        for (int j = 0; j < 16; j++) {
            const int tile = j >> 2;
            const int qq = (j & 3) * 256 + tid;
            const int r = qq >> 3;          // row 0..127
            const int cch = qq & 7;         // 16B chunk within 128B row
            const __half* g;
            if      (tile == 0) g = gsrc0 + (size_t)r * Kdim + kt + cch * 8;
            else if (tile == 1) g = gsrc1 + (size_t)r * Kdim + kt + cch * 8;
            else if (tile == 2) g = gsrc2 + (size_t)r * Kdim + kt + cch * 8;
            else                g = gsrc3 + (size_t)r * Kdim + kt + cch * 8;
            cp16(sbase + buf * BUFB + tile * TILEB + r * ROWB + cch * 16, g);
        }
        cp_commit();
    };

    issue(0, 0);

    // per-lane ldmatrix address components (loop invariant)
    const int arow = wm * 64 + (lane & 15);
    const int akof = (lane >> 4) * 8;
    const int brow = wn * 32 + (lane & 7);
    const int bkof = ((lane >> 3) & 1) * 8;

    for (int t = 0; t < nTiles; ++t) {
        if (t + 1 < nTiles) {
            issue((t + 1) & 1, (t + 1) * HBK);
            cp_wait<1>();
        } else {
            cp_wait<0>();
        }
        __syncthreads();

        const uint32_t bufb = sbase + (t & 1) * BUFB;
        const uint32_t aBhi = bufb;
        const uint32_t aBlo = bufb + TILEB;
        const uint32_t bBhi = bufb + 2 * TILEB;
        const uint32_t bBlo = bufb + 3 * TILEB;

        uint32_t ah[2][4][4], bh[2][4][2];   // double-buffered hi fragments
        uint32_t al[4][4],    bl[4][2];      // single-buffered lo fragments

        // preload hi fragments for group 0
#pragma unroll
        for (int bn = 0; bn < 4; bn++)
            ldsm_x2(bh[0][bn], bBhi + (uint32_t)(brow + bn * 8) * ROWB + bkof * 2);
#pragma unroll
        for (int am = 0; am < 4; am++)
            ldsm_x4(ah[0][am], aBhi + (uint32_t)(arow + am * 16) * ROWB + akof * 2);

#pragma unroll
        for (int g = 0; g < HBK / 16; ++g) {
            const int ks  = g * 16;
            const int cur = g & 1;
            const int nxt = cur ^ 1;
            // lo fragments for current group
#pragma unroll
            for (int bn = 0; bn < 4; bn++)
                ldsm_x2(bl[bn], bBlo + (uint32_t)(brow + bn * 8) * ROWB + (ks + bkof) * 2);
#pragma unroll
            for (int am = 0; am < 4; am++)
                ldsm_x4(al[am], aBlo + (uint32_t)(arow + am * 16) * ROWB + (ks + akof) * 2);
            // hi * hi
#pragma unroll
            for (int am = 0; am < 4; am++)
#pragma unroll
                for (int bn = 0; bn < 4; bn++)
                    mma16816(acc[am][bn], ah[cur][am], bh[cur][bn]);
            // prefetch next group's hi fragments
            if (g + 1 < HBK / 16) {
                const int ks2 = ks + 16;
#pragma unroll
                for (int bn = 0; bn < 4; bn++)
                    ldsm_x2(bh[nxt][bn], bBhi + (uint32_t)(brow + bn * 8) * ROWB + (ks2 + bkof) * 2);
#pragma unroll
                for (int am = 0; am < 4; am++)
                    ldsm_x4(ah[nxt][am], aBhi + (uint32_t)(arow + am * 16) * ROWB + (ks2 + akof) * 2);
            }
            // hi * lo
#pragma unroll
            for (int am = 0; am < 4; am++)
#pragma unroll
                for (int bn = 0; bn < 4; bn++)
                    mma16816(acc[am][bn], ah[cur][am], bl[bn]);
            // lo * hi
#pragma unroll
            for (int am = 0; am < 4; am++)
#pragma unroll
                for (int bn = 0; bn < 4; bn++)
                    mma16816(acc[am][bn], al[am], bh[cur][bn]);
        }
        __syncthreads();
    }

    // ---- epilogue ----
#pragma unroll
    for (int am = 0; am < 4; am++) {
#pragma unroll
        for (int bn = 0; bn < 4; bn++) {
            const int row = m0 + wm * 64 + am * 16 + (lane >> 2);
            const int col = n0 + wn * 32 + bn * 8 + (lane & 3) * 2;
            float v[4];
#pragma unroll
            for (int k = 0; k < 4; k++) v[k] = acc[am][bn][k] * scale;
            if (bias) {
                const float bx = bias[col], by = bias[col + 1];
                v[0] += bx; v[1] += by; v[2] += bx; v[3] += by;
            }
            if (ACT == 1) {
#pragma unroll
                for (int k = 0; k < 4; k++) v[k] = gelu_exact(v[k]);
            }
            if (OUT_SPLIT == 1) {
#pragma unroll
                for (int half_row = 0; half_row < 2; half_row++) {
                    const size_t base = (size_t)(row + half_row * 8) * ldc + col;
                    const float v0 = v[half_row * 2], v1 = v[half_row * 2 + 1];
                    const __half h0 = __float2half_rn(v0);
                    const __half h1 = __float2half_rn(v1);
                    __half2 hhi = __halves2half2(h0, h1);
                    __half2 hlo = __halves2half2(__float2half_rn(v0 - __half2float(h0)),
                                                 __float2half_rn(v1 - __half2float(h1)));
                    *(__half2*)(Chi + base) = hhi;
                    *(__half2*)(Clo + base) = hlo;
                }
            } else {
                *(float2*)(Cf + (size_t)row * ldc + col) = make_float2(v[0], v[1]);
                *(float2*)(Cf + (size_t)(row + 8) * ldc + col) = make_float2(v[2], v[3]);
            }
        }
    }
}

// ---------------- fp32 -> fp16 hi/lo split (elementwise) ----------------
__global__ __launch_bounds__(256)
void split_kernel(const float* __restrict__ in, __half* __restrict__ hi,
                  __half* __restrict__ lo, int n)
{
    int i = blockIdx.x * 256 + threadIdx.x;
    if (i < n) {
        float x = in[i];
        __half h = __float2half_rn(x);
        hi[i] = h;
        lo[i] = __float2half_rn(x - __half2float(h));
    }
}

// ---------------- W [K,N] fp32 -> transposed [N,K] hi/lo half splits ----------------
__global__ void splitT_kernel(const float* __restrict__ in,
                              __half* __restrict__ hi, __half* __restrict__ lo)
{
    __shared__ float tile[32][33];
    const int x = blockIdx.x * 32 + threadIdx.x;   // N index in input
#pragma unroll
    for (int dy = threadIdx.y; dy < 32; dy += 8)
        tile[dy][threadIdx.x] = in[(size_t)(blockIdx.y * 32 + dy) * DD + x];
    __syncthreads();
    const int k = blockIdx.y * 32 + threadIdx.x;   // K index in output (contiguous)
#pragma unroll
    for (int dy = threadIdx.y; dy < 32; dy += 8) {
        const int n = blockIdx.x * 32 + dy;
        const float v = tile[threadIdx.x][dy];
        const __half h = __float2half_rn(v);
        hi[(size_t)n * DD + k] = h;
        lo[(size_t)n * DD + k] = __float2half_rn(v - __half2float(h));
    }
}

// ---------------- fused Sinkhorn iteration ----------------
// FIRST=1 (iteration 1): per-row max-tracked LSE for r; per-column running
// (m,s) LSE accumulators in registers (underflow-safe); writes pm/ps partials.
// FIRST=0 (iterations 2+): entries bounded (<= ~0 after normalization), so
// plain exp-sums; writes plain column partial sums to p1.
template <int FIRST>
__global__ __launch_bounds__(256)
void sink_iter_kernel(const float* __restrict__ S, float* __restrict__ r,
                      const float* __restrict__ c,
                      float* __restrict__ p1, float* __restrict__ p2)
{
    __shared__ float sc[NR];
    __shared__ float red[8];
    const int tid = threadIdx.x;

    if (!FIRST) {
        for (int j = tid; j < NR / 4; j += 256)
            ((float4*)sc)[j] = ((const float4*)c)[j];
        __syncthreads();
    }

    float4 accs[8];   // plain sums (FIRST=0) or LSE 's' (FIRST=1)
    float4 accm[8];   // LSE 'm' (FIRST=1 only)
#pragma unroll
    for (int k = 0; k < 8; ++k) {
        accs[k] = make_float4(0.f, 0.f, 0.f, 0.f);
        if (FIRST) accm[k] = make_float4(-INFINITY, -INFINITY, -INFINITY, -INFINITY);
    }

    const int i0 = blockIdx.x * FRPB;
    for (int ii = 0; ii < FRPB; ++ii) {
        const int i = i0 + ii;
        const float4* row = (const float4*)(S + (size_t)i * NR);
        float4 v[8];
#pragma unroll
        for (int k = 0; k < 8; ++k) v[k] = row[tid + 256 * k];

        if (FIRST) {
            // block row-max
            float mx = -INFINITY;
#pragma unroll
            for (int k = 0; k < 8; ++k) {
                mx = fmaxf(mx, fmaxf(fmaxf(v[k].x, v[k].y), fmaxf(v[k].z, v[k].w)));
            }
#pragma unroll
            for (int o = 16; o > 0; o >>= 1) mx = fmaxf(mx, __shfl_xor_sync(0xffffffffu, mx, o));
            if ((tid & 31) == 0) red[tid >> 5] = mx;
            __syncthreads();
            mx = red[0];
#pragma unroll
            for (int w = 1; w < 8; ++w) mx = fmaxf(mx, red[w]);
            __syncthreads();
            // row sum of exp(v - mx)
            float s = 0.0f;
#pragma unroll
            for (int k = 0; k < 8; ++k) {
                s += __expf(v[k].x - mx) + __expf(v[k].y - mx)
                   + __expf(v[k].z - mx) + __expf(v[k].w - mx);
            }
#pragma unroll
            for (int o = 16; o > 0; o >>= 1) s += __shfl_xor_sync(0xffffffffu, s, o);
            if ((tid & 31) == 0) red[tid >> 5] = s;
            __syncthreads();
            float t = red[0];
#pragma unroll
            for (int w = 1; w < 8; ++w) t += red[w];
            const float ri = mx + logf(t);
            if (tid == 0) r[i] = ri;
            __syncthreads();
            // column LSE accumulate of (v - ri)
#pragma unroll
            for (int k = 0; k < 8; ++k) {
                lse_add(accm[k].x, accs[k].x, v[k].x - ri);
                lse_add(accm[k].y, accs[k].y, v[k].y - ri);
                lse_add(accm[k].z, accs[k].z, v[k].z - ri);
                lse_add(accm[k].w, accs[k].w, v[k].w - ri);
            }
        } else {
            const float ri = __ldg(&r[i]);
            float4 e[8];
            float s = 0.0f;
#pragma unroll
            for (int k = 0; k < 8; ++k) {
                float4 cc = ((const float4*)sc)[tid + 256 * k];
                e[k].x = __expf(v[k].x - cc.x - ri);
                e[k].y = __expf(v[k].y - cc.y - ri);
                e[k].z = __expf(v[k].z - cc.z - ri);
                e[k].w = __expf(v[k].w - cc.w - ri);
                s += (e[k].x + e[k].y) + (e[k].z + e[k].w);
            }
#pragma unroll
            for (int o = 16; o > 0; o >>= 1) s += __shfl_xor_sync(0xffffffffu, s, o);
            if ((tid & 31) == 0) red[tid >> 5] = s;
            __syncthreads();
            float t = red[0];
#pragma unroll
            for (int w = 1; w < 8; ++w) t += red[w];
            if (tid == 0) r[i] = ri + logf(t);
            __syncthreads();
            const float inv = 1.0f / t;
#pragma unroll
            for (int k = 0; k < 8; ++k) {
                accs[k].x += e[k].x * inv;
                accs[k].y += e[k].y * inv;
                accs[k].z += e[k].z * inv;
                accs[k].w += e[k].w * inv;
            }
        }
    }
    float4* o1 = (float4*)(p1 + (size_t)blockIdx.x * NR);
    if (FIRST) {
        float4* o2 = (float4*)(p2 + (size_t)blockIdx.x * NR);
#pragma unroll
        for (int k = 0; k < 8; ++k) { o1[tid + 256 * k] = accm[k]; o2[tid + 256 * k] = accs[k]; }
    } else {
#pragma unroll
        for (int k = 0; k < 8; ++k) o1[tid + 256 * k] = accs[k];
    }
}

// ---------------- combine iter-1 column LSE partials: c = m + log(s) ----------------
// grid NR/64, block 256: 64 columns/block, 4 sub-reducers x 128 chunks each.
__global__ __launch_bounds__(256)
void first_combine_kernel(const float* __restrict__ pm, const float* __restrict__ ps,
                          float* __restrict__ c)
{
    __shared__ float sm[4][64], ss[4][64];
    const int tid = threadIdx.x;
    const int jj  = tid & 63;
    const int sub = tid >> 6;
    const int j   = blockIdx.x * 64 + jj;
    float m = -INFINITY, s = 0.0f;
#pragma unroll 4
    for (int b = sub * (FNBLK / 4); b < (sub + 1) * (FNBLK / 4); ++b)
        lse_merge(m, s, pm[(size_t)b * NR + j], ps[(size_t)b * NR + j]);
    sm[sub][jj] = m; ss[sub][jj] = s;
    __syncthreads();
    if (tid < 64) {
        float m0 = sm[0][tid], s0 = ss[0][tid];
        lse_merge(m0, s0, sm[1][tid], ss[1][tid]);
        lse_merge(m0, s0, sm[2][tid], ss[2][tid]);
        lse_merge(m0, s0, sm[3][tid], ss[3][tid]);
        c[blockIdx.x * 64 + tid] = m0 + logf(s0);
    }
}

// ---------------- combine plain column partials: c += log(sum) ----------------
__global__ __launch_bounds__(256)
void sink_combine_kernel(const float* __restrict__ part, float* __restrict__ c)
{
    __shared__ float ss[4][64];
    const int tid = threadIdx.x;
    const int jj  = tid & 63;
    const int sub = tid >> 6;
    const int j   = blockIdx.x * 64 + jj;
    float s = 0.0f;
#pragma unroll 8
    for (int b = sub * (FNBLK / 4); b < (sub + 1) * (FNBLK / 4); ++b)
        s += part[(size_t)b * NR + j];
    ss[sub][jj] = s;
    __syncthreads();
    if (tid < 64) {
        float t = ss[0][tid] + ss[1][tid] + ss[2][tid] + ss[3][tid];
        c[blockIdx.x * 64 + tid] += logf(t);
    }
}

// ---------------- output: out = exp(S - r_i - c_j) ----------------
__global__ __launch_bounds__(256)
void out_exp_kernel(const float* __restrict__ S, const float* __restrict__ r,
                    const float* __restrict__ c, float* __restrict__ out)
{
    const size_t nq = (size_t)NR * NR / 4;
    const float4* S4 = (const float4*)S;
    const float4* c4 = (const float4*)c;
    float4* o4 = (float4*)out;
    size_t idx = (size_t)blockIdx.x * blockDim.x + threadIdx.x;
    const size_t stride = (size_t)gridDim.x * blockDim.x;
    for (; idx < nq; idx += stride) {
        size_t i  = idx / (NR / 4);
        size_t jq = idx % (NR / 4);
        float ri = r[i];
        float4 cc = c4[jq];
        float4 v = S4[idx];
        float4 o;
        o.x = __expf(v.x - ri - cc.x);
        o.y = __expf(v.y - ri - cc.y);
        o.z = __expf(v.z - ri - cc.z);
        o.w = __expf(v.w - ri - cc.w);
        o4[idx] = o;
    }
}

// ---------------- launch ----------------
extern "C" void kernel_launch(void* const* d_in, const int* in_sizes, int n_in,
                              void* d_out, int out_size)
{
    const float* emb_a = (const float*)d_in[0];
    const float* emb_b = (const float*)d_in[1];
    const float* W1    = (const float*)d_in[2];
    const float* b1    = (const float*)d_in[3];
    const float* W2    = (const float*)d_in[4];
    const float* b2    = (const float*)d_in[5];
    float* out = (float*)d_out;

    float *scores, *r, *c, *pm, *ps;
    __half *x_hi, *x_lo, *h_hi, *h_lo, *a_hi, *a_lo, *b_hi, *b_lo;
    __half *w1_hi, *w1_lo, *w2_hi, *w2_lo;
    cudaGetSymbolAddress((void**)&scores, g_scores);
    cudaGetSymbolAddress((void**)&x_hi, g_x_hi);
    cudaGetSymbolAddress((void**)&x_lo, g_x_lo);
    cudaGetSymbolAddress((void**)&h_hi, g_h_hi);
    cudaGetSymbolAddress((void**)&h_lo, g_h_lo);
    cudaGetSymbolAddress((void**)&a_hi, g_a_hi);
    cudaGetSymbolAddress((void**)&a_lo, g_a_lo);
    cudaGetSymbolAddress((void**)&b_hi, g_b_hi);
    cudaGetSymbolAddress((void**)&b_lo, g_b_lo);
    cudaGetSymbolAddress((void**)&w1_hi, g_w1_hi);
    cudaGetSymbolAddress((void**)&w1_lo, g_w1_lo);
    cudaGetSymbolAddress((void**)&w2_hi, g_w2_hi);
    cudaGetSymbolAddress((void**)&w2_lo, g_w2_lo);
    cudaGetSymbolAddress((void**)&r,  g_r);
    cudaGetSymbolAddress((void**)&c,  g_c);
    cudaGetSymbolAddress((void**)&pm, g_pm);
    cudaGetSymbolAddress((void**)&ps, g_ps);

    cudaFuncSetAttribute(hmma_kernel<1, 1>,
                         cudaFuncAttributeMaxDynamicSharedMemorySize, SMEM_HMMA);
    cudaFuncSetAttribute(hmma_kernel<0, 1>,
                         cudaFuncAttributeMaxDynamicSharedMemorySize, SMEM_HMMA);
    cudaFuncSetAttribute(hmma_kernel<0, 0>,
                         cudaFuncAttributeMaxDynamicSharedMemorySize, SMEM_HMMA);

    const int nel = NR * DD;
    const dim3 gProj(DD / 128, NR / 128);     // (8, 64)
    const dim3 gScore(NR / 128, NR / 128);    // (64, 64)

    // weight split + transpose to [N, K]
    splitT_kernel<<<dim3(32, 32), dim3(32, 8)>>>(W1, w1_hi, w1_lo);
    splitT_kernel<<<dim3(32, 32), dim3(32, 8)>>>(W2, w2_hi, w2_lo);

    // branch a: emb_a -> gelu(xW1+b1) -> (hW2+b2) as splits
    split_kernel<<<nel / 256, 256>>>(emb_a, x_hi, x_lo, nel);
    hmma_kernel<1, 1><<<gProj, 256, SMEM_HMMA>>>(x_hi, x_lo, w1_hi, w1_lo, b1,
                                                 nullptr, h_hi, h_lo, DD, DD, 1.0f);
    hmma_kernel<0, 1><<<gProj, 256, SMEM_HMMA>>>(h_hi, h_lo, w2_hi, w2_lo, b2,
                                                 nullptr, a_hi, a_lo, DD, DD, 1.0f);
    // branch b
    split_kernel<<<nel / 256, 256>>>(emb_b, x_hi, x_lo, nel);
    hmma_kernel<1, 1><<<gProj, 256, SMEM_HMMA>>>(x_hi, x_lo, w1_hi, w1_lo, b1,
                                                 nullptr, h_hi, h_lo, DD, DD, 1.0f);
    hmma_kernel<0, 1><<<gProj, 256, SMEM_HMMA>>>(h_hi, h_lo, w2_hi, w2_lo, b2,
                                                 nullptr, b_hi, b_lo, DD, DD, 1.0f);

    // scores = 20 * a @ b^T
    hmma_kernel<0, 0><<<gScore, 256, SMEM_HMMA>>>(a_hi, a_lo, b_hi, b_lo, nullptr,
                                                  scores, nullptr, nullptr, NR, DD,
                                                  INV_TEMP);

    // Sinkhorn iteration 1: fused row LSE + column LSE partials (underflow-safe)
    sink_iter_kernel<1><<<FNBLK, 256>>>(scores, r, nullptr, pm, ps);
    first_combine_kernel<<<NR / 64, 256>>>(pm, ps, c);

    // iterations 2..20: fused single-pass with plain sums
    for (int it = 1; it < ITERS; ++it) {
        sink_iter_kernel<0><<<FNBLK, 256>>>(scores, r, c, pm, nullptr);
        sink_combine_kernel<<<NR / 64, 256>>>(pm, c);
    }

    // final output
    out_exp_kernel<<<2048, 256>>>(scores, r, c, out);
}

// round 12
// speedup vs baseline: 1.6538x; 1.0683x over previous
#include <cuda_runtime.h>
#include <cuda_fp16.h>
#include <math.h>
#include <stdint.h>

// Problem constants
#define NR 8192
#define DD 1024
#define ITERS 20
#define INV_TEMP 20.0f

// Sinkhorn blocking: 592 = 4 * 148 SMs -> clean 4-wave schedule
#define SINK_NBLK 592
#define SINK_FULL 496          // blocks 0..495 take 14 rows, rest take 13

// HMMA tiling: BM=BN=128, BK=64, 512 threads, 16 warps (4 M x 4 N), warp tile 32x32
#define HBK 64
#define ROWB 144                      // padded row stride in bytes (64 halfs + 16 pad)
#define TILEB (128 * ROWB)            // 18432 B per operand tile
#define BUFB (4 * TILEB)              // 73728 B per stage (Ahi,Alo,Bhi,Blo)
#define SMEM_HMMA (2 * BUFB)          // 147456 B double buffered

// ---------------- device scratch (static, no allocation) ----------------
__device__ float g_scores[(size_t)NR * NR];   // 256 MB
__device__ __half g_x_hi[(size_t)2 * NR * DD];
__device__ __half g_x_lo[(size_t)2 * NR * DD];
__device__ __half g_h_hi[(size_t)2 * NR * DD];
__device__ __half g_h_lo[(size_t)2 * NR * DD];
__device__ __half g_ab_hi[(size_t)2 * NR * DD];   // rows 0..NR-1 = a, NR.. = b
__device__ __half g_ab_lo[(size_t)2 * NR * DD];
__device__ __half g_w1_hi[(size_t)DD * DD];
__device__ __half g_w1_lo[(size_t)DD * DD];
__device__ __half g_w2_hi[(size_t)DD * DD];
__device__ __half g_w2_lo[(size_t)DD * DD];
__device__ float g_r[NR];
__device__ float g_c[NR];
__device__ float g_pm[(size_t)SINK_NBLK * NR];
__device__ float g_ps[(size_t)SINK_NBLK * NR];

// ---------------- small helpers ----------------
__device__ __forceinline__ uint32_t smem_to_u32(const void* smem_ptr) {
    uint32_t addr;
    asm("{ .reg .u64 tmp; cvta.to.shared.u64 tmp, %1; cvt.u32.u64 %0, tmp; }"
        : "=r"(addr) : "l"(smem_ptr));
    return addr;
}
__device__ __forceinline__ void cp16(uint32_t saddr, const void* g) {
    asm volatile("cp.async.cg.shared.global [%0], [%1], 16;" :: "r"(saddr), "l"(g));
}
__device__ __forceinline__ void cp_commit() {
    asm volatile("cp.async.commit_group;");
}
template <int N> __device__ __forceinline__ void cp_wait() {
    asm volatile("cp.async.wait_group %0;" :: "n"(N));
}
__device__ __forceinline__ void ldsm_x4(uint32_t* r, uint32_t addr) {
    asm volatile("ldmatrix.sync.aligned.m8n8.x4.shared.b16 {%0,%1,%2,%3}, [%4];"
                 : "=r"(r[0]), "=r"(r[1]), "=r"(r[2]), "=r"(r[3]) : "r"(addr));
}
__device__ __forceinline__ void ldsm_x2(uint32_t* r, uint32_t addr) {
    asm volatile("ldmatrix.sync.aligned.m8n8.x2.shared.b16 {%0,%1}, [%2];"
                 : "=r"(r[0]), "=r"(r[1]) : "r"(addr));
}
__device__ __forceinline__ void mma16816(float* c, const uint32_t* a, const uint32_t* b) {
    asm volatile(
        "mma.sync.aligned.m16n8k16.row.col.f32.f16.f16.f32 "
        "{%0,%1,%2,%3}, {%4,%5,%6,%7}, {%8,%9}, {%0,%1,%2,%3};"
        : "+f"(c[0]), "+f"(c[1]), "+f"(c[2]), "+f"(c[3])
        : "r"(a[0]), "r"(a[1]), "r"(a[2]), "r"(a[3]), "r"(b[0]), "r"(b[1]));
}
__device__ __forceinline__ float gelu_exact(float x) {
    return 0.5f * x * (1.0f + erff(x * 0.70710678118654752440f));
}
__device__ __forceinline__ void lse_add(float& m, float& s, float v) {
    if (v <= m) { s += __expf(v - m); }
    else        { s = s * __expf(m - v) + 1.0f; m = v; }
}
__device__ __forceinline__ void lse_merge(float& m1, float& s1, float m2, float s2) {
    if (m2 == -INFINITY) return;
    if (m1 == -INFINITY) { m1 = m2; s1 = s2; return; }
    if (m2 <= m1) { s1 += s2 * __expf(m2 - m1); }
    else { s1 = s1 * __expf(m1 - m2) + s2; m1 = m2; }
}

// ---------------- HMMA GEMM: C = epilogue(scale*(A @ B^T) [+ bias]) ----------------
// 512 threads, 16 warps (4x4), warp tile 32x32 -> acc 32 f/thread, ~95 regs,
// 4 warps/SMSP for latency hiding. BK=64 double-buffered smem (147KB, 1 CTA/SM).
template <int ACT, int OUT_SPLIT>
__global__ __launch_bounds__(512)
void hmma_kernel(const __half* __restrict__ Ah, const __half* __restrict__ Al,
                 const __half* __restrict__ Bh, const __half* __restrict__ Bl,
                 const float* __restrict__ bias,
                 float* __restrict__ Cf, __half* __restrict__ Chi, __half* __restrict__ Clo,
                 int ldc, int Kdim, float scale)
{
    extern __shared__ __align__(16) char smem[];
    const uint32_t sbase = smem_to_u32(smem);
    const int tid  = threadIdx.x;
    const int warp = tid >> 5;
    const int lane = tid & 31;
    const int wm = warp >> 2;       // 0..3 (32-row slab)
    const int wn = warp & 3;        // 0..3 (32-col slab)

    const int m0 = blockIdx.y * 128;
    const int n0 = blockIdx.x * 128;

    const __half* gsrc0 = Ah + (size_t)m0 * Kdim;
    const __half* gsrc1 = Al + (size_t)m0 * Kdim;
    const __half* gsrc2 = Bh + (size_t)n0 * Kdim;
    const __half* gsrc3 = Bl + (size_t)n0 * Kdim;

    float acc[2][4][4];
#pragma unroll
    for (int i = 0; i < 2; i++)
#pragma unroll
        for (int j = 0; j < 4; j++)
#pragma unroll
            for (int k = 0; k < 4; k++) acc[i][j][k] = 0.0f;

    const int nTiles = Kdim / HBK;

    // ---- async tile loader: 8 x 16B chunks per thread per stage ----
    // Each operand tile: 128 rows x 128B = 1024 chunks = 2 rounds of 512 thr.
    auto issue = [&](int buf, int kt) {
#pragma unroll
        for (int j = 0; j < 8; j++) {
            const int tile = j >> 1;
            const int qq = (j & 1) * 512 + tid;
            const int r = qq >> 3;          // row 0..127
            const int cch = qq & 7;         // 16B chunk within 128B row
            const __half* g;
            if      (tile == 0) g = gsrc0 + (size_t)r * Kdim + kt + cch * 8;
            else if (tile == 1) g = gsrc1 + (size_t)r * Kdim + kt + cch * 8;
            else if (tile == 2) g = gsrc2 + (size_t)r * Kdim + kt + cch * 8;
            else                g = gsrc3 + (size_t)r * Kdim + kt + cch * 8;
            cp16(sbase + buf * BUFB + tile * TILEB + r * ROWB + cch * 16, g);
        }
        cp_commit();
    };

    issue(0, 0);

    // per-lane ldmatrix address components (loop invariant)
    const int arow = wm * 32 + (lane & 15);
    const int akof = (lane >> 4) * 8;
    const int brow = wn * 32 + (lane & 7);
    const int bkof = ((lane >> 3) & 1) * 8;

    for (int t = 0; t < nTiles; ++t) {
        if (t + 1 < nTiles) {
            issue((t + 1) & 1, (t + 1) * HBK);
            cp_wait<1>();
        } else {
            cp_wait<0>();
        }
        __syncthreads();

        const uint32_t bufb = sbase + (t & 1) * BUFB;
        const uint32_t aBhi = bufb;
        const uint32_t aBlo = bufb + TILEB;
        const uint32_t bBhi = bufb + 2 * TILEB;
        const uint32_t bBlo = bufb + 3 * TILEB;

#pragma unroll
        for (int ks = 0; ks < HBK; ks += 16) {
            uint32_t ah[2][4], al[2][4], bh[4][2], bl[4][2];
#pragma unroll
            for (int am = 0; am < 2; am++) {
                const uint32_t off = (uint32_t)(arow + am * 16) * ROWB + (ks + akof) * 2;
                ldsm_x4(ah[am], aBhi + off);
                ldsm_x4(al[am], aBlo + off);
            }
#pragma unroll
            for (int bn = 0; bn < 4; bn++) {
                const uint32_t off = (uint32_t)(brow + bn * 8) * ROWB + (ks + bkof) * 2;
                ldsm_x2(bh[bn], bBhi + off);
                ldsm_x2(bl[bn], bBlo + off);
            }
            // hi*hi
#pragma unroll
            for (int am = 0; am < 2; am++)
#pragma unroll
                for (int bn = 0; bn < 4; bn++)
                    mma16816(acc[am][bn], ah[am], bh[bn]);
            // hi*lo
#pragma unroll
            for (int am = 0; am < 2; am++)
#pragma unroll
                for (int bn = 0; bn < 4; bn++)
                    mma16816(acc[am][bn], ah[am], bl[bn]);
            // lo*hi
#pragma unroll
            for (int am = 0; am < 2; am++)
#pragma unroll
                for (int bn = 0; bn < 4; bn++)
                    mma16816(acc[am][bn], al[am], bh[bn]);
        }
        __syncthreads();
    }

    // ---- epilogue ----
#pragma unroll
    for (int am = 0; am < 2; am++) {
#pragma unroll
        for (int bn = 0; bn < 4; bn++) {
            const int row = m0 + wm * 32 + am * 16 + (lane >> 2);
            const int col = n0 + wn * 32 + bn * 8 + (lane & 3) * 2;
            float v[4];
#pragma unroll
            for (int k = 0; k < 4; k++) v[k] = acc[am][bn][k] * scale;
            if (bias) {
                const float bx = bias[col], by = bias[col + 1];
                v[0] += bx; v[1] += by; v[2] += bx; v[3] += by;
            }
            if (ACT == 1) {
#pragma unroll
                for (int k = 0; k < 4; k++) v[k] = gelu_exact(v[k]);
            }
            if (OUT_SPLIT == 1) {
#pragma unroll
                for (int half_row = 0; half_row < 2; half_row++) {
                    const size_t base = (size_t)(row + half_row * 8) * ldc + col;
                    const float v0 = v[half_row * 2], v1 = v[half_row * 2 + 1];
                    const __half h0 = __float2half_rn(v0);
                    const __half h1 = __float2half_rn(v1);
                    __half2 hhi = __halves2half2(h0, h1);
                    __half2 hlo = __halves2half2(__float2half_rn(v0 - __half2float(h0)),
                                                 __float2half_rn(v1 - __half2float(h1)));
                    *(__half2*)(Chi + base) = hhi;
                    *(__half2*)(Clo + base) = hlo;
                }
            } else {
                *(float2*)(Cf + (size_t)row * ldc + col) = make_float2(v[0], v[1]);
                *(float2*)(Cf + (size_t)(row + 8) * ldc + col) = make_float2(v[2], v[3]);
            }
        }
    }
}

// ---------------- fp32 -> fp16 hi/lo split (elementwise) ----------------
__global__ __launch_bounds__(256)
void split_kernel(const float* __restrict__ in, __half* __restrict__ hi,
                  __half* __restrict__ lo, int n)
{
    int i = blockIdx.x * 256 + threadIdx.x;
    if (i < n) {
        float x = in[i];
        __half h = __float2half_rn(x);
        hi[i] = h;
        lo[i] = __float2half_rn(x - __half2float(h));
    }
}

// ---------------- W [K,N] fp32 -> transposed [N,K] hi/lo half splits ----------------
__global__ void splitT_kernel(const float* __restrict__ in,
                              __half* __restrict__ hi, __half* __restrict__ lo)
{
    __shared__ float tile[32][33];
    const int x = blockIdx.x * 32 + threadIdx.x;   // N index in input
#pragma unroll
    for (int dy = threadIdx.y; dy < 32; dy += 8)
        tile[dy][threadIdx.x] = in[(size_t)(blockIdx.y * 32 + dy) * DD + x];
    __syncthreads();
    const int k = blockIdx.y * 32 + threadIdx.x;   // K index in output (contiguous)
#pragma unroll
    for (int dy = threadIdx.y; dy < 32; dy += 8) {
        const int n = blockIdx.x * 32 + dy;
        const float v = tile[threadIdx.x][dy];
        const __half h = __float2half_rn(v);
        hi[(size_t)n * DD + k] = h;
        lo[(size_t)n * DD + k] = __float2half_rn(v - __half2float(h));
    }
}

// ---------------- fused Sinkhorn iteration ----------------
// Variable rows per block: blocks [0,SINK_FULL) take 14 rows, rest 13 (592 = 4 waves).
// FIRST=1: max-tracked row LSE + per-column register LSE accumulators.
// FIRST=0: plain exp-sums (entries bounded after iteration 1).
template <int FIRST>
__global__ __launch_bounds__(256)
void sink_iter_kernel(const float* __restrict__ S, float* __restrict__ r,
                      const float* __restrict__ c,
                      float* __restrict__ p1, float* __restrict__ p2)
{
    __shared__ float sc[NR];
    __shared__ float red[8];
    const int tid = threadIdx.x;
    const int bid = blockIdx.x;

    if (!FIRST) {
        for (int j = tid; j < NR / 4; j += 256)
            ((float4*)sc)[j] = ((const float4*)c)[j];
        __syncthreads();
    }

    float4 accs[8];
    float4 accm[8];
#pragma unroll
    for (int k = 0; k < 8; ++k) {
        accs[k] = make_float4(0.f, 0.f, 0.f, 0.f);
        if (FIRST) accm[k] = make_float4(-INFINITY, -INFINITY, -INFINITY, -INFINITY);
    }

    const int nrows = 13 + (bid < SINK_FULL ? 1 : 0);
    const int i0 = (bid < SINK_FULL) ? bid * 14 : SINK_FULL * 14 + (bid - SINK_FULL) * 13;

    for (int ii = 0; ii < nrows; ++ii) {
        const int i = i0 + ii;
        const float4* row = (const float4*)(S + (size_t)i * NR);
        float4 v[8];
#pragma unroll
        for (int k = 0; k < 8; ++k) v[k] = row[tid + 256 * k];

        if (FIRST) {
            float mx = -INFINITY;
#pragma unroll
            for (int k = 0; k < 8; ++k)
                mx = fmaxf(mx, fmaxf(fmaxf(v[k].x, v[k].y), fmaxf(v[k].z, v[k].w)));
#pragma unroll
            for (int o = 16; o > 0; o >>= 1) mx = fmaxf(mx, __shfl_xor_sync(0xffffffffu, mx, o));
            if ((tid & 31) == 0) red[tid >> 5] = mx;
            __syncthreads();
            mx = red[0];
#pragma unroll
            for (int w = 1; w < 8; ++w) mx = fmaxf(mx, red[w]);
            __syncthreads();
            float s = 0.0f;
#pragma unroll
            for (int k = 0; k < 8; ++k) {
                s += __expf(v[k].x - mx) + __expf(v[k].y - mx)
                   + __expf(v[k].z - mx) + __expf(v[k].w - mx);
            }
#pragma unroll
            for (int o = 16; o > 0; o >>= 1) s += __shfl_xor_sync(0xffffffffu, s, o);
            if ((tid & 31) == 0) red[tid >> 5] = s;
            __syncthreads();
            float t = red[0];
#pragma unroll
            for (int w = 1; w < 8; ++w) t += red[w];
            const float ri = mx + logf(t);
            if (tid == 0) r[i] = ri;
            __syncthreads();
#pragma unroll
            for (int k = 0; k < 8; ++k) {
                lse_add(accm[k].x, accs[k].x, v[k].x - ri);
                lse_add(accm[k].y, accs[k].y, v[k].y - ri);
                lse_add(accm[k].z, accs[k].z, v[k].z - ri);
                lse_add(accm[k].w, accs[k].w, v[k].w - ri);
            }
        } else {
            const float ri = __ldg(&r[i]);
            float4 e[8];
            float s = 0.0f;
#pragma unroll
            for (int k = 0; k < 8; ++k) {
                float4 cc = ((const float4*)sc)[tid + 256 * k];
                e[k].x = __expf(v[k].x - cc.x - ri);
                e[k].y = __expf(v[k].y - cc.y - ri);
                e[k].z = __expf(v[k].z - cc.z - ri);
                e[k].w = __expf(v[k].w - cc.w - ri);
                s += (e[k].x + e[k].y) + (e[k].z + e[k].w);
            }
#pragma unroll
            for (int o = 16; o > 0; o >>= 1) s += __shfl_xor_sync(0xffffffffu, s, o);
            if ((tid & 31) == 0) red[tid >> 5] = s;
            __syncthreads();
            // every thread sums the 8 warp partials (no second barrier)
            float t = red[0];
#pragma unroll
            for (int w = 1; w < 8; ++w) t += red[w];
            if (tid == 0) r[i] = ri + logf(t);
            __syncthreads();
            const float inv = 1.0f / t;
#pragma unroll
            for (int k = 0; k < 8; ++k) {
                accs[k].x += e[k].x * inv;
                accs[k].y += e[k].y * inv;
                accs[k].z += e[k].z * inv;
                accs[k].w += e[k].w * inv;
            }
        }
    }
    float4* o1 = (float4*)(p1 + (size_t)bid * NR);
    if (FIRST) {
        float4* o2 = (float4*)(p2 + (size_t)bid * NR);
#pragma unroll
        for (int k = 0; k < 8; ++k) { o1[tid + 256 * k] = accm[k]; o2[tid + 256 * k] = accs[k]; }
    } else {
#pragma unroll
        for (int k = 0; k < 8; ++k) o1[tid + 256 * k] = accs[k];
    }
}

// ---------------- combine iter-1 column LSE partials: c = m + log(s) ----------------
__global__ __launch_bounds__(256)
void first_combine_kernel(const float* __restrict__ pm, const float* __restrict__ ps,
                          float* __restrict__ c)
{
    __shared__ float sm[4][64], ss[4][64];
    const int tid = threadIdx.x;
    const int jj  = tid & 63;
    const int sub = tid >> 6;
    const int j   = blockIdx.x * 64 + jj;
    float m = -INFINITY, s = 0.0f;
    for (int b = sub * (SINK_NBLK / 4); b < (sub + 1) * (SINK_NBLK / 4); ++b)
        lse_merge(m, s, pm[(size_t)b * NR + j], ps[(size_t)b * NR + j]);
    sm[sub][jj] = m; ss[sub][jj] = s;
    __syncthreads();
    if (tid < 64) {
        float m0 = sm[0][tid], s0 = ss[0][tid];
        lse_merge(m0, s0, sm[1][tid], ss[1][tid]);
        lse_merge(m0, s0, sm[2][tid], ss[2][tid]);
        lse_merge(m0, s0, sm[3][tid], ss[3][tid]);
        c[blockIdx.x * 64 + tid] = m0 + logf(s0);
    }
}

// ---------------- combine plain column partials: c += log(sum) ----------------
__global__ __launch_bounds__(256)
void sink_combine_kernel(const float* __restrict__ part, float* __restrict__ c)
{
    __shared__ float ss[4][64];
    const int tid = threadIdx.x;
    const int jj  = tid & 63;
    const int sub = tid >> 6;
    const int j   = blockIdx.x * 64 + jj;
    float s = 0.0f;
    for (int b = sub * (SINK_NBLK / 4); b < (sub + 1) * (SINK_NBLK / 4); ++b)
        s += part[(size_t)b * NR + j];
    ss[sub][jj] = s;
    __syncthreads();
    if (tid < 64) {
        float t = ss[0][tid] + ss[1][tid] + ss[2][tid] + ss[3][tid];
        c[blockIdx.x * 64 + tid] += logf(t);
    }
}

// ---------------- output: out = exp(S - r_i - c_j) ----------------
__global__ __launch_bounds__(256)
void out_exp_kernel(const float* __restrict__ S, const float* __restrict__ r,
                    const float* __restrict__ c, float* __restrict__ out)
{
    const size_t nq = (size_t)NR * NR / 4;
    const float4* S4 = (const float4*)S;
    const float4* c4 = (const float4*)c;
    float4* o4 = (float4*)out;
    size_t idx = (size_t)blockIdx.x * blockDim.x + threadIdx.x;
    const size_t stride = (size_t)gridDim.x * blockDim.x;
    for (; idx < nq; idx += stride) {
        size_t i  = idx / (NR / 4);
        size_t jq = idx % (NR / 4);
        float ri = r[i];
        float4 cc = c4[jq];
        float4 v = S4[idx];
        float4 o;
        o.x = __expf(v.x - ri - cc.x);
        o.y = __expf(v.y - ri - cc.y);
        o.z = __expf(v.z - ri - cc.z);
        o.w = __expf(v.w - ri - cc.w);
        o4[idx] = o;
    }
}

// ---------------- launch ----------------
extern "C" void kernel_launch(void* const* d_in, const int* in_sizes, int n_in,
                              void* d_out, int out_size)
{
    const float* emb_a = (const float*)d_in[0];
    const float* emb_b = (const float*)d_in[1];
    const float* W1    = (const float*)d_in[2];
    const float* b1    = (const float*)d_in[3];
    const float* W2    = (const float*)d_in[4];
    const float* b2    = (const float*)d_in[5];
    float* out = (float*)d_out;

    float *scores, *r, *c, *pm, *ps;
    __half *x_hi, *x_lo, *h_hi, *h_lo, *ab_hi, *ab_lo;
    __half *w1_hi, *w1_lo, *w2_hi, *w2_lo;
    cudaGetSymbolAddress((void**)&scores, g_scores);
    cudaGetSymbolAddress((void**)&x_hi, g_x_hi);
    cudaGetSymbolAddress((void**)&x_lo, g_x_lo);
    cudaGetSymbolAddress((void**)&h_hi, g_h_hi);
    cudaGetSymbolAddress((void**)&h_lo, g_h_lo);
    cudaGetSymbolAddress((void**)&ab_hi, g_ab_hi);
    cudaGetSymbolAddress((void**)&ab_lo, g_ab_lo);
    cudaGetSymbolAddress((void**)&w1_hi, g_w1_hi);
    cudaGetSymbolAddress((void**)&w1_lo, g_w1_lo);
    cudaGetSymbolAddress((void**)&w2_hi, g_w2_hi);
    cudaGetSymbolAddress((void**)&w2_lo, g_w2_lo);
    cudaGetSymbolAddress((void**)&r,  g_r);
    cudaGetSymbolAddress((void**)&c,  g_c);
    cudaGetSymbolAddress((void**)&pm, g_pm);
    cudaGetSymbolAddress((void**)&ps, g_ps);

    cudaFuncSetAttribute(hmma_kernel<1, 1>,
                         cudaFuncAttributeMaxDynamicSharedMemorySize, SMEM_HMMA);
    cudaFuncSetAttribute(hmma_kernel<0, 1>,
                         cudaFuncAttributeMaxDynamicSharedMemorySize, SMEM_HMMA);
    cudaFuncSetAttribute(hmma_kernel<0, 0>,
                         cudaFuncAttributeMaxDynamicSharedMemorySize, SMEM_HMMA);

    const int nel = NR * DD;

    // weight split + transpose to [N, K]
    splitT_kernel<<<dim3(32, 32), dim3(32, 8)>>>(W1, w1_hi, w1_lo);
    splitT_kernel<<<dim3(32, 32), dim3(32, 8)>>>(W2, w2_hi, w2_lo);

    // both embeddings into one [2*NR, DD] split buffer
    split_kernel<<<nel / 256, 256>>>(emb_a, x_hi, x_lo, nel);
    split_kernel<<<nel / 256, 256>>>(emb_b, x_hi + (size_t)nel, x_lo + (size_t)nel, nel);

    // batched projections: [2*NR, DD] once through each layer
    const dim3 gProj(DD / 128, 2 * NR / 128);   // (8, 128)
    hmma_kernel<1, 1><<<gProj, 512, SMEM_HMMA>>>(x_hi, x_lo, w1_hi, w1_lo, b1,
                                                 nullptr, h_hi, h_lo, DD, DD, 1.0f);
    hmma_kernel<0, 1><<<gProj, 512, SMEM_HMMA>>>(h_hi, h_lo, w2_hi, w2_lo, b2,
                                                 nullptr, ab_hi, ab_lo, DD, DD, 1.0f);

    // scores = 20 * a @ b^T  (a = ab rows 0..NR-1, b = rows NR..2NR-1)
    const dim3 gScore(NR / 128, NR / 128);      // (64, 64)
    hmma_kernel<0, 0><<<gScore, 512, SMEM_HMMA>>>(ab_hi, ab_lo,
                                                  ab_hi + (size_t)nel, ab_lo + (size_t)nel,
                                                  nullptr, scores, nullptr, nullptr,
                                                  NR, DD, INV_TEMP);

    // Sinkhorn iteration 1: fused row LSE + column LSE partials (underflow-safe)
    sink_iter_kernel<1><<<SINK_NBLK, 256>>>(scores, r, nullptr, pm, ps);
    first_combine_kernel<<<NR / 64, 256>>>(pm, ps, c);

    // iterations 2..20: fused single-pass with plain sums
    for (int it = 1; it < ITERS; ++it) {
        sink_iter_kernel<0><<<SINK_NBLK, 256>>>(scores, r, c, pm, nullptr);
        sink_combine_kernel<<<NR / 64, 256>>>(pm, c);
    }

    // final output
    out_exp_kernel<<<2048, 256>>>(scores, r, c, out);
}

// round 13
// speedup vs baseline: 1.6887x; 1.0211x over previous
#include <cuda_runtime.h>
#include <cuda_fp16.h>
#include <math.h>
#include <stdint.h>

// Problem constants
#define NR 8192
#define DD 1024
#define ITERS 20
#define INV_TEMP 20.0f

// Sinkhorn blocking: 592 = 4 * 148 SMs -> clean 4-wave schedule
#define SINK_NBLK 592
#define SINK_FULL 496          // blocks 0..495 take 14 rows, rest take 13

// HMMA tiling: BM=BN=128, BK=64, 512 threads, 16 warps (4 M x 4 N), warp tile 32x32
#define HBK 64
#define ROWB 144                      // padded row stride in bytes (64 halfs + 16 pad)
#define TILEB (128 * ROWB)            // 18432 B per operand tile
#define BUFB (4 * TILEB)              // 73728 B per stage (Ahi,Alo,Bhi,Blo)
#define NSTAGE 3
#define SMEM_HMMA (NSTAGE * BUFB)     // 221184 B triple buffered

// ---------------- device scratch (static, no allocation) ----------------
__device__ float g_scores[(size_t)NR * NR];   // 256 MB
__device__ __half g_x_hi[(size_t)2 * NR * DD];
__device__ __half g_x_lo[(size_t)2 * NR * DD];
__device__ __half g_h_hi[(size_t)2 * NR * DD];
__device__ __half g_h_lo[(size_t)2 * NR * DD];
__device__ __half g_ab_hi[(size_t)2 * NR * DD];   // rows 0..NR-1 = a, NR.. = b
__device__ __half g_ab_lo[(size_t)2 * NR * DD];
__device__ __half g_w1_hi[(size_t)DD * DD];
__device__ __half g_w1_lo[(size_t)DD * DD];
__device__ __half g_w2_hi[(size_t)DD * DD];
__device__ __half g_w2_lo[(size_t)DD * DD];
__device__ float g_r[NR];
__device__ float g_c[NR];
__device__ float g_pm[(size_t)SINK_NBLK * NR];
__device__ float g_ps[(size_t)SINK_NBLK * NR];

// ---------------- small helpers ----------------
__device__ __forceinline__ uint32_t smem_to_u32(const void* smem_ptr) {
    uint32_t addr;
    asm("{ .reg .u64 tmp; cvta.to.shared.u64 tmp, %1; cvt.u32.u64 %0, tmp; }"
        : "=r"(addr) : "l"(smem_ptr));
    return addr;
}
__device__ __forceinline__ void cp16(uint32_t saddr, const void* g) {
    asm volatile("cp.async.cg.shared.global [%0], [%1], 16;" :: "r"(saddr), "l"(g));
}
__device__ __forceinline__ void cp_commit() {
    asm volatile("cp.async.commit_group;");
}
template <int N> __device__ __forceinline__ void cp_wait() {
    asm volatile("cp.async.wait_group %0;" :: "n"(N));
}
__device__ __forceinline__ void ldsm_x4(uint32_t* r, uint32_t addr) {
    asm volatile("ldmatrix.sync.aligned.m8n8.x4.shared.b16 {%0,%1,%2,%3}, [%4];"
                 : "=r"(r[0]), "=r"(r[1]), "=r"(r[2]), "=r"(r[3]) : "r"(addr));
}
__device__ __forceinline__ void mma16816(float* c, const uint32_t* a, const uint32_t* b) {
    asm volatile(
        "mma.sync.aligned.m16n8k16.row.col.f32.f16.f16.f32 "
        "{%0,%1,%2,%3}, {%4,%5,%6,%7}, {%8,%9}, {%0,%1,%2,%3};"
        : "+f"(c[0]), "+f"(c[1]), "+f"(c[2]), "+f"(c[3])
        : "r"(a[0]), "r"(a[1]), "r"(a[2]), "r"(a[3]), "r"(b[0]), "r"(b[1]));
}
__device__ __forceinline__ float gelu_exact(float x) {
    return 0.5f * x * (1.0f + erff(x * 0.70710678118654752440f));
}
__device__ __forceinline__ void lse_add(float& m, float& s, float v) {
    if (v <= m) { s += __expf(v - m); }
    else        { s = s * __expf(m - v) + 1.0f; m = v; }
}
__device__ __forceinline__ void lse_merge(float& m1, float& s1, float m2, float s2) {
    if (m2 == -INFINITY) return;
    if (m1 == -INFINITY) { m1 = m2; s1 = s2; return; }
    if (m2 <= m1) { s1 += s2 * __expf(m2 - m1); }
    else { s1 = s1 * __expf(m1 - m2) + s2; m1 = m2; }
}

// ---------------- HMMA GEMM: C = epilogue(scale*(A @ B^T) [+ bias]) ----------------
// 512 threads, 16 warps (4x4), warp tile 32x32.
// B fragments via ldsm.x4 pairs (8 LDSM per warp per K-step, down from 12);
// 3-stage cp.async pipeline (221KB smem) keeps two tiles in flight.
template <int ACT, int OUT_SPLIT>
__global__ __launch_bounds__(512)
void hmma_kernel(const __half* __restrict__ Ah, const __half* __restrict__ Al,
                 const __half* __restrict__ Bh, const __half* __restrict__ Bl,
                 const float* __restrict__ bias,
                 float* __restrict__ Cf, __half* __restrict__ Chi, __half* __restrict__ Clo,
                 int ldc, int Kdim, float scale)
{
    extern __shared__ __align__(16) char smem[];
    const uint32_t sbase = smem_to_u32(smem);
    const int tid  = threadIdx.x;
    const int warp = tid >> 5;
    const int lane = tid & 31;
    const int wm = warp >> 2;       // 0..3 (32-row slab)
    const int wn = warp & 3;        // 0..3 (32-col slab)

    const int m0 = blockIdx.y * 128;
    const int n0 = blockIdx.x * 128;

    const __half* gsrc0 = Ah + (size_t)m0 * Kdim;
    const __half* gsrc1 = Al + (size_t)m0 * Kdim;
    const __half* gsrc2 = Bh + (size_t)n0 * Kdim;
    const __half* gsrc3 = Bl + (size_t)n0 * Kdim;

    float acc[2][4][4];
#pragma unroll
    for (int i = 0; i < 2; i++)
#pragma unroll
        for (int j = 0; j < 4; j++)
#pragma unroll
            for (int k = 0; k < 4; k++) acc[i][j][k] = 0.0f;

    const int nTiles = Kdim / HBK;

    // ---- async tile loader: 8 x 16B chunks per thread per stage ----
    auto issue = [&](int buf, int kt) {
#pragma unroll
        for (int j = 0; j < 8; j++) {
            const int tile = j >> 1;
            const int qq = (j & 1) * 512 + tid;
            const int r = qq >> 3;          // row 0..127
            const int cch = qq & 7;         // 16B chunk within 128B row
            const __half* g;
            if      (tile == 0) g = gsrc0 + (size_t)r * Kdim + kt + cch * 8;
            else if (tile == 1) g = gsrc1 + (size_t)r * Kdim + kt + cch * 8;
            else if (tile == 2) g = gsrc2 + (size_t)r * Kdim + kt + cch * 8;
            else                g = gsrc3 + (size_t)r * Kdim + kt + cch * 8;
            cp16(sbase + buf * BUFB + tile * TILEB + r * ROWB + cch * 16, g);
        }
        cp_commit();
    };

    issue(0, 0);
    if (nTiles > 1) issue(1, HBK);

    // per-lane ldmatrix address components (loop invariant)
    const int arow  = wm * 32 + (lane & 15);
    const int akof  = (lane >> 4) * 8;
    // B x4 mapping: mat0/1 = n-rows p*16+0..7 (k-low/k-high), mat2/3 = rows +8
    const int brow4 = wn * 32 + ((lane >> 4) & 1) * 8 + (lane & 7);
    const int bk4   = ((lane >> 3) & 1) * 8;

    for (int t = 0; t < nTiles; ++t) {
        if (t + 2 < nTiles) {
            issue((t + 2) % NSTAGE, (t + 2) * HBK);
            cp_wait<2>();
        } else if (t + 1 < nTiles) {
            cp_wait<1>();
        } else {
            cp_wait<0>();
        }
        __syncthreads();

        const uint32_t bufb = sbase + (t % NSTAGE) * BUFB;
        const uint32_t aBhi = bufb;
        const uint32_t aBlo = bufb + TILEB;
        const uint32_t bBhi = bufb + 2 * TILEB;
        const uint32_t bBlo = bufb + 3 * TILEB;

#pragma unroll
        for (int ks = 0; ks < HBK; ks += 16) {
            uint32_t ah[2][4], al[2][4], bh[4][2], bl[4][2];
#pragma unroll
            for (int am = 0; am < 2; am++) {
                const uint32_t off = (uint32_t)(arow + am * 16) * ROWB + (ks + akof) * 2;
                ldsm_x4(ah[am], aBhi + off);
                ldsm_x4(al[am], aBlo + off);
            }
            // B: two x4 loads cover bn pairs (0,1) and (2,3), hi and lo
#pragma unroll
            for (int p = 0; p < 2; p++) {
                const uint32_t off = (uint32_t)(brow4 + p * 16) * ROWB + (ks + bk4) * 2;
                ldsm_x4(&bh[p * 2][0], bBhi + off);
                ldsm_x4(&bl[p * 2][0], bBlo + off);
            }
            // hi*hi
#pragma unroll
            for (int am = 0; am < 2; am++)
#pragma unroll
                for (int bn = 0; bn < 4; bn++)
                    mma16816(acc[am][bn], ah[am], bh[bn]);
            // hi*lo
#pragma unroll
            for (int am = 0; am < 2; am++)
#pragma unroll
                for (int bn = 0; bn < 4; bn++)
                    mma16816(acc[am][bn], ah[am], bl[bn]);
            // lo*hi
#pragma unroll
            for (int am = 0; am < 2; am++)
#pragma unroll
                for (int bn = 0; bn < 4; bn++)
                    mma16816(acc[am][bn], al[am], bh[bn]);
        }
        __syncthreads();
    }

    // ---- epilogue ----
#pragma unroll
    for (int am = 0; am < 2; am++) {
#pragma unroll
        for (int bn = 0; bn < 4; bn++) {
            const int row = m0 + wm * 32 + am * 16 + (lane >> 2);
            const int col = n0 + wn * 32 + bn * 8 + (lane & 3) * 2;
            float v[4];
#pragma unroll
            for (int k = 0; k < 4; k++) v[k] = acc[am][bn][k] * scale;
            if (bias) {
                const float bx = bias[col], by = bias[col + 1];
                v[0] += bx; v[1] += by; v[2] += bx; v[3] += by;
            }
            if (ACT == 1) {
#pragma unroll
                for (int k = 0; k < 4; k++) v[k] = gelu_exact(v[k]);
            }
            if (OUT_SPLIT == 1) {
#pragma unroll
                for (int half_row = 0; half_row < 2; half_row++) {
                    const size_t base = (size_t)(row + half_row * 8) * ldc + col;
                    const float v0 = v[half_row * 2], v1 = v[half_row * 2 + 1];
                    const __half h0 = __float2half_rn(v0);
                    const __half h1 = __float2half_rn(v1);
                    __half2 hhi = __halves2half2(h0, h1);
                    __half2 hlo = __halves2half2(__float2half_rn(v0 - __half2float(h0)),
                                                 __float2half_rn(v1 - __half2float(h1)));
                    *(__half2*)(Chi + base) = hhi;
                    *(__half2*)(Clo + base) = hlo;
                }
            } else {
                *(float2*)(Cf + (size_t)row * ldc + col) = make_float2(v[0], v[1]);
                *(float2*)(Cf + (size_t)(row + 8) * ldc + col) = make_float2(v[2], v[3]);
            }
        }
    }
}

// ---------------- fp32 -> fp16 hi/lo split (elementwise) ----------------
__global__ __launch_bounds__(256)
void split_kernel(const float* __restrict__ in, __half* __restrict__ hi,
                  __half* __restrict__ lo, int n)
{
    int i = blockIdx.x * 256 + threadIdx.x;
    if (i < n) {
        float x = in[i];
        __half h = __float2half_rn(x);
        hi[i] = h;
        lo[i] = __float2half_rn(x - __half2float(h));
    }
}

// ---------------- W [K,N] fp32 -> transposed [N,K] hi/lo half splits ----------------
__global__ void splitT_kernel(const float* __restrict__ in,
                              __half* __restrict__ hi, __half* __restrict__ lo)
{
    __shared__ float tile[32][33];
    const int x = blockIdx.x * 32 + threadIdx.x;   // N index in input
#pragma unroll
    for (int dy = threadIdx.y; dy < 32; dy += 8)
        tile[dy][threadIdx.x] = in[(size_t)(blockIdx.y * 32 + dy) * DD + x];
    __syncthreads();
    const int k = blockIdx.y * 32 + threadIdx.x;   // K index in output (contiguous)
#pragma unroll
    for (int dy = threadIdx.y; dy < 32; dy += 8) {
        const int n = blockIdx.x * 32 + dy;
        const float v = tile[threadIdx.x][dy];
        const __half h = __float2half_rn(v);
        hi[(size_t)n * DD + k] = h;
        lo[(size_t)n * DD + k] = __float2half_rn(v - __half2float(h));
    }
}

// ---------------- fused Sinkhorn iteration ----------------
// Variable rows per block: blocks [0,SINK_FULL) take 14 rows, rest 13 (592 = 4 waves).
// FIRST=1: max-tracked row LSE + per-column register LSE accumulators.
// FIRST=0: plain exp-sums (entries bounded after iteration 1).
template <int FIRST>
__global__ __launch_bounds__(256)
void sink_iter_kernel(const float* __restrict__ S, float* __restrict__ r,
                      const float* __restrict__ c,
                      float* __restrict__ p1, float* __restrict__ p2)
{
    __shared__ float sc[NR];
    __shared__ float red[8];
    const int tid = threadIdx.x;
    const int bid = blockIdx.x;

    if (!FIRST) {
        for (int j = tid; j < NR / 4; j += 256)
            ((float4*)sc)[j] = ((const float4*)c)[j];
        __syncthreads();
    }

    float4 accs[8];
    float4 accm[8];
#pragma unroll
    for (int k = 0; k < 8; ++k) {
        accs[k] = make_float4(0.f, 0.f, 0.f, 0.f);
        if (FIRST) accm[k] = make_float4(-INFINITY, -INFINITY, -INFINITY, -INFINITY);
    }

    const int nrows = 13 + (bid < SINK_FULL ? 1 : 0);
    const int i0 = (bid < SINK_FULL) ? bid * 14 : SINK_FULL * 14 + (bid - SINK_FULL) * 13;

    for (int ii = 0; ii < nrows; ++ii) {
        const int i = i0 + ii;
        const float4* row = (const float4*)(S + (size_t)i * NR);
        float4 v[8];
#pragma unroll
        for (int k = 0; k < 8; ++k) v[k] = row[tid + 256 * k];

        if (FIRST) {
            float mx = -INFINITY;
#pragma unroll
            for (int k = 0; k < 8; ++k)
                mx = fmaxf(mx, fmaxf(fmaxf(v[k].x, v[k].y), fmaxf(v[k].z, v[k].w)));
#pragma unroll
            for (int o = 16; o > 0; o >>= 1) mx = fmaxf(mx, __shfl_xor_sync(0xffffffffu, mx, o));
            if ((tid & 31) == 0) red[tid >> 5] = mx;
            __syncthreads();
            mx = red[0];
#pragma unroll
            for (int w = 1; w < 8; ++w) mx = fmaxf(mx, red[w]);
            __syncthreads();
            float s = 0.0f;
#pragma unroll
            for (int k = 0; k < 8; ++k) {
                s += __expf(v[k].x - mx) + __expf(v[k].y - mx)
                   + __expf(v[k].z - mx) + __expf(v[k].w - mx);
            }
#pragma unroll
            for (int o = 16; o > 0; o >>= 1) s += __shfl_xor_sync(0xffffffffu, s, o);
            if ((tid & 31) == 0) red[tid >> 5] = s;
            __syncthreads();
            float t = red[0];
#pragma unroll
            for (int w = 1; w < 8; ++w) t += red[w];
            const float ri = mx + logf(t);
            if (tid == 0) r[i] = ri;
            __syncthreads();
#pragma unroll
            for (int k = 0; k < 8; ++k) {
                lse_add(accm[k].x, accs[k].x, v[k].x - ri);
                lse_add(accm[k].y, accs[k].y, v[k].y - ri);
                lse_add(accm[k].z, accs[k].z, v[k].z - ri);
                lse_add(accm[k].w, accs[k].w, v[k].w - ri);
            }
        } else {
            const float ri = __ldg(&r[i]);
            float4 e[8];
            float s = 0.0f;
#pragma unroll
            for (int k = 0; k < 8; ++k) {
                float4 cc = ((const float4*)sc)[tid + 256 * k];
                e[k].x = __expf(v[k].x - cc.x - ri);
                e[k].y = __expf(v[k].y - cc.y - ri);
                e[k].z = __expf(v[k].z - cc.z - ri);
                e[k].w = __expf(v[k].w - cc.w - ri);
                s += (e[k].x + e[k].y) + (e[k].z + e[k].w);
            }
#pragma unroll
            for (int o = 16; o > 0; o >>= 1) s += __shfl_xor_sync(0xffffffffu, s, o);
            if ((tid & 31) == 0) red[tid >> 5] = s;
            __syncthreads();
            float t = red[0];
#pragma unroll
            for (int w = 1; w < 8; ++w) t += red[w];
            if (tid == 0) r[i] = ri + logf(t);
            __syncthreads();
            const float inv = 1.0f / t;
#pragma unroll
            for (int k = 0; k < 8; ++k) {
                accs[k].x += e[k].x * inv;
                accs[k].y += e[k].y * inv;
                accs[k].z += e[k].z * inv;
                accs[k].w += e[k].w * inv;
            }
        }
    }
    float4* o1 = (float4*)(p1 + (size_t)bid * NR);
    if (FIRST) {
        float4* o2 = (float4*)(p2 + (size_t)bid * NR);
#pragma unroll
        for (int k = 0; k < 8; ++k) { o1[tid + 256 * k] = accm[k]; o2[tid + 256 * k] = accs[k]; }
    } else {
#pragma unroll
        for (int k = 0; k < 8; ++k) o1[tid + 256 * k] = accs[k];
    }
}

// ---------------- combine iter-1 column LSE partials: c = m + log(s) ----------------
__global__ __launch_bounds__(256)
void first_combine_kernel(const float* __restrict__ pm, const float* __restrict__ ps,
                          float* __restrict__ c)
{
    __shared__ float sm[4][64], ss[4][64];
    const int tid = threadIdx.x;
    const int jj  = tid & 63;
    const int sub = tid >> 6;
    const int j   = blockIdx.x * 64 + jj;
    float m = -INFINITY, s = 0.0f;
    for (int b = sub * (SINK_NBLK / 4); b < (sub + 1) * (SINK_NBLK / 4); ++b)
        lse_merge(m, s, pm[(size_t)b * NR + j], ps[(size_t)b * NR + j]);
    sm[sub][jj] = m; ss[sub][jj] = s;
    __syncthreads();
    if (tid < 64) {
        float m0 = sm[0][tid], s0 = ss[0][tid];
        lse_merge(m0, s0, sm[1][tid], ss[1][tid]);
        lse_merge(m0, s0, sm[2][tid], ss[2][tid]);
        lse_merge(m0, s0, sm[3][tid], ss[3][tid]);
        c[blockIdx.x * 64 + tid] = m0 + logf(s0);
    }
}

// ---------------- combine plain column partials: c += log(sum) ----------------
__global__ __launch_bounds__(256)
void sink_combine_kernel(const float* __restrict__ part, float* __restrict__ c)
{
    __shared__ float ss[4][64];
    const int tid = threadIdx.x;
    const int jj  = tid & 63;
    const int sub = tid >> 6;
    const int j   = blockIdx.x * 64 + jj;
    float s = 0.0f;
    for (int b = sub * (SINK_NBLK / 4); b < (sub + 1) * (SINK_NBLK / 4); ++b)
        s += part[(size_t)b * NR + j];
    ss[sub][jj] = s;
    __syncthreads();
    if (tid < 64) {
        float t = ss[0][tid] + ss[1][tid] + ss[2][tid] + ss[3][tid];
        c[blockIdx.x * 64 + tid] += logf(t);
    }
}

// ---------------- output: out = exp(S - r_i - c_j) ----------------
__global__ __launch_bounds__(256)
void out_exp_kernel(const float* __restrict__ S, const float* __restrict__ r,
                    const float* __restrict__ c, float* __restrict__ out)
{
    const size_t nq = (size_t)NR * NR / 4;
    const float4* S4 = (const float4*)S;
    const float4* c4 = (const float4*)c;
    float4* o4 = (float4*)out;
    size_t idx = (size_t)blockIdx.x * blockDim.x + threadIdx.x;
    const size_t stride = (size_t)gridDim.x * blockDim.x;
    for (; idx < nq; idx += stride) {
        size_t i  = idx / (NR / 4);
        size_t jq = idx % (NR / 4);
        float ri = r[i];
        float4 cc = c4[jq];
        float4 v = S4[idx];
        float4 o;
        o.x = __expf(v.x - ri - cc.x);
        o.y = __expf(v.y - ri - cc.y);
        o.z = __expf(v.z - ri - cc.z);
        o.w = __expf(v.w - ri - cc.w);
        o4[idx] = o;
    }
}

// ---------------- launch ----------------
extern "C" void kernel_launch(void* const* d_in, const int* in_sizes, int n_in,
                              void* d_out, int out_size)
{
    const float* emb_a = (const float*)d_in[0];
    const float* emb_b = (const float*)d_in[1];
    const float* W1    = (const float*)d_in[2];
    const float* b1    = (const float*)d_in[3];
    const float* W2    = (const float*)d_in[4];
    const float* b2    = (const float*)d_in[5];
    float* out = (float*)d_out;

    float *scores, *r, *c, *pm, *ps;
    __half *x_hi, *x_lo, *h_hi, *h_lo, *ab_hi, *ab_lo;
    __half *w1_hi, *w1_lo, *w2_hi, *w2_lo;
    cudaGetSymbolAddress((void**)&scores, g_scores);
    cudaGetSymbolAddress((void**)&x_hi, g_x_hi);
    cudaGetSymbolAddress((void**)&x_lo, g_x_lo);
    cudaGetSymbolAddress((void**)&h_hi, g_h_hi);
    cudaGetSymbolAddress((void**)&h_lo, g_h_lo);
    cudaGetSymbolAddress((void**)&ab_hi, g_ab_hi);
    cudaGetSymbolAddress((void**)&ab_lo, g_ab_lo);
    cudaGetSymbolAddress((void**)&w1_hi, g_w1_hi);
    cudaGetSymbolAddress((void**)&w1_lo, g_w1_lo);
    cudaGetSymbolAddress((void**)&w2_hi, g_w2_hi);
    cudaGetSymbolAddress((void**)&w2_lo, g_w2_lo);
    cudaGetSymbolAddress((void**)&r,  g_r);
    cudaGetSymbolAddress((void**)&c,  g_c);
    cudaGetSymbolAddress((void**)&pm, g_pm);
    cudaGetSymbolAddress((void**)&ps, g_ps);

    cudaFuncSetAttribute(hmma_kernel<1, 1>,
                         cudaFuncAttributeMaxDynamicSharedMemorySize, SMEM_HMMA);
    cudaFuncSetAttribute(hmma_kernel<0, 1>,
                         cudaFuncAttributeMaxDynamicSharedMemorySize, SMEM_HMMA);
    cudaFuncSetAttribute(hmma_kernel<0, 0>,
                         cudaFuncAttributeMaxDynamicSharedMemorySize, SMEM_HMMA);

    const int nel = NR * DD;

    // weight split + transpose to [N, K]
    splitT_kernel<<<dim3(32, 32), dim3(32, 8)>>>(W1, w1_hi, w1_lo);
    splitT_kernel<<<dim3(32, 32), dim3(32, 8)>>>(W2, w2_hi, w2_lo);

    // both embeddings into one [2*NR, DD] split buffer
    split_kernel<<<nel / 256, 256>>>(emb_a, x_hi, x_lo, nel);
    split_kernel<<<nel / 256, 256>>>(emb_b, x_hi + (size_t)nel, x_lo + (size_t)nel, nel);

    // batched projections: [2*NR, DD] once through each layer
    const dim3 gProj(DD / 128, 2 * NR / 128);   // (8, 128)
    hmma_kernel<1, 1><<<gProj, 512, SMEM_HMMA>>>(x_hi, x_lo, w1_hi, w1_lo, b1,
                                                 nullptr, h_hi, h_lo, DD, DD, 1.0f);
    hmma_kernel<0, 1><<<gProj, 512, SMEM_HMMA>>>(h_hi, h_lo, w2_hi, w2_lo, b2,
                                                 nullptr, ab_hi, ab_lo, DD, DD, 1.0f);

    // scores = 20 * a @ b^T  (a = ab rows 0..NR-1, b = rows NR..2NR-1)
    const dim3 gScore(NR / 128, NR / 128);      // (64, 64)
    hmma_kernel<0, 0><<<gScore, 512, SMEM_HMMA>>>(ab_hi, ab_lo,
                                                  ab_hi + (size_t)nel, ab_lo + (size_t)nel,
                                                  nullptr, scores, nullptr, nullptr,
                                                  NR, DD, INV_TEMP);

    // Sinkhorn iteration 1: fused row LSE + column LSE partials (underflow-safe)
    sink_iter_kernel<1><<<SINK_NBLK, 256>>>(scores, r, nullptr, pm, ps);
    first_combine_kernel<<<NR / 64, 256>>>(pm, ps, c);

    // iterations 2..20: fused single-pass with plain sums
    for (int it = 1; it < ITERS; ++it) {
        sink_iter_kernel<0><<<SINK_NBLK, 256>>>(scores, r, c, pm, nullptr);
        sink_combine_kernel<<<NR / 64, 256>>>(pm, c);
    }

    // final output
    out_exp_kernel<<<2048, 256>>>(scores, r, c, out);
}

// round 14
// speedup vs baseline: 1.7645x; 1.0448x over previous
#include <cuda_runtime.h>
#include <cuda_fp16.h>
#include <math.h>
#include <stdint.h>

// Problem constants
#define NR 8192
#define DD 1024
#define ITERS 20
#define INV_TEMP 20.0f

// Sinkhorn blocking: 592 = 4 * 148 SMs -> clean 4-wave schedule
#define SINK_NBLK 592
#define SINK_FULL 496          // blocks 0..495 take 14 rows, rest take 13

// HMMA tiling: BM=BN=128, BK=64, 512 threads, 16 warps (4 M x 4 N), warp tile 32x32
#define HBK 64
#define ROWB 144                      // padded row stride in bytes (64 halfs + 16 pad)
#define TILEB (128 * ROWB)            // 18432 B per operand tile
#define BUFB (4 * TILEB)              // 73728 B per stage (Ahi,Alo,Bhi,Blo)
#define NSTAGE 3
#define SMEM_HMMA (NSTAGE * BUFB)     // 221184 B triple buffered

// ---------------- device scratch (static, no allocation) ----------------
__device__ float g_scores[(size_t)NR * NR];   // 256 MB
__device__ __half g_x_hi[(size_t)2 * NR * DD];
__device__ __half g_x_lo[(size_t)2 * NR * DD];
__device__ __half g_h_hi[(size_t)2 * NR * DD];
__device__ __half g_h_lo[(size_t)2 * NR * DD];
__device__ __half g_ab_hi[(size_t)2 * NR * DD];   // rows 0..NR-1 = a, NR.. = b
__device__ __half g_ab_lo[(size_t)2 * NR * DD];
__device__ __half g_w1_hi[(size_t)DD * DD];
__device__ __half g_w1_lo[(size_t)DD * DD];
__device__ __half g_w2_hi[(size_t)DD * DD];
__device__ __half g_w2_lo[(size_t)DD * DD];
__device__ float g_r[NR];
__device__ float g_c[NR];
__device__ float g_pm[(size_t)SINK_NBLK * NR];
__device__ float g_ps[(size_t)SINK_NBLK * NR];

// ---------------- small helpers ----------------
__device__ __forceinline__ uint32_t smem_to_u32(const void* smem_ptr) {
    uint32_t addr;
    asm("{ .reg .u64 tmp; cvta.to.shared.u64 tmp, %1; cvt.u32.u64 %0, tmp; }"
        : "=r"(addr) : "l"(smem_ptr));
    return addr;
}
__device__ __forceinline__ void cp16(uint32_t saddr, const void* g) {
    asm volatile("cp.async.cg.shared.global [%0], [%1], 16;" :: "r"(saddr), "l"(g));
}
__device__ __forceinline__ void cp_commit() {
    asm volatile("cp.async.commit_group;");
}
template <int N> __device__ __forceinline__ void cp_wait() {
    asm volatile("cp.async.wait_group %0;" :: "n"(N));
}
__device__ __forceinline__ void ldsm_x4(uint32_t* r, uint32_t addr) {
    asm volatile("ldmatrix.sync.aligned.m8n8.x4.shared.b16 {%0,%1,%2,%3}, [%4];"
                 : "=r"(r[0]), "=r"(r[1]), "=r"(r[2]), "=r"(r[3]) : "r"(addr));
}
__device__ __forceinline__ void mma16816(float* c, const uint32_t* a, const uint32_t* b) {
    asm volatile(
        "mma.sync.aligned.m16n8k16.row.col.f32.f16.f16.f32 "
        "{%0,%1,%2,%3}, {%4,%5,%6,%7}, {%8,%9}, {%0,%1,%2,%3};"
        : "+f"(c[0]), "+f"(c[1]), "+f"(c[2]), "+f"(c[3])
        : "r"(a[0]), "r"(a[1]), "r"(a[2]), "r"(a[3]), "r"(b[0]), "r"(b[1]));
}
__device__ __forceinline__ float gelu_exact(float x) {
    return 0.5f * x * (1.0f + erff(x * 0.70710678118654752440f));
}
__device__ __forceinline__ void lse_add(float& m, float& s, float v) {
    if (v <= m) { s += __expf(v - m); }
    else        { s = s * __expf(m - v) + 1.0f; m = v; }
}
__device__ __forceinline__ void lse_merge(float& m1, float& s1, float m2, float s2) {
    if (m2 == -INFINITY) return;
    if (m1 == -INFINITY) { m1 = m2; s1 = s2; return; }
    if (m2 <= m1) { s1 += s2 * __expf(m2 - m1); }
    else { s1 = s1 * __expf(m1 - m2) + s2; m1 = m2; }
}

// ---------------- HMMA GEMM: C = epilogue(scale*(A @ B^T) [+ bias]) ----------------
// 512 threads, 16 warps (4x4), warp tile 32x32.
// B fragments via ldsm.x4 pairs; 3-stage cp.async pipeline (221KB smem).
template <int ACT, int OUT_SPLIT>
__global__ __launch_bounds__(512)
void hmma_kernel(const __half* __restrict__ Ah, const __half* __restrict__ Al,
                 const __half* __restrict__ Bh, const __half* __restrict__ Bl,
                 const float* __restrict__ bias,
                 float* __restrict__ Cf, __half* __restrict__ Chi, __half* __restrict__ Clo,
                 int ldc, int Kdim, float scale)
{
    extern __shared__ __align__(16) char smem[];
    const uint32_t sbase = smem_to_u32(smem);
    const int tid  = threadIdx.x;
    const int warp = tid >> 5;
    const int lane = tid & 31;
    const int wm = warp >> 2;       // 0..3 (32-row slab)
    const int wn = warp & 3;        // 0..3 (32-col slab)

    const int m0 = blockIdx.y * 128;
    const int n0 = blockIdx.x * 128;

    const __half* gsrc0 = Ah + (size_t)m0 * Kdim;
    const __half* gsrc1 = Al + (size_t)m0 * Kdim;
    const __half* gsrc2 = Bh + (size_t)n0 * Kdim;
    const __half* gsrc3 = Bl + (size_t)n0 * Kdim;

    float acc[2][4][4];
#pragma unroll
    for (int i = 0; i < 2; i++)
#pragma unroll
        for (int j = 0; j < 4; j++)
#pragma unroll
            for (int k = 0; k < 4; k++) acc[i][j][k] = 0.0f;

    const int nTiles = Kdim / HBK;

    // ---- async tile loader: 8 x 16B chunks per thread per stage ----
    auto issue = [&](int buf, int kt) {
#pragma unroll
        for (int j = 0; j < 8; j++) {
            const int tile = j >> 1;
            const int qq = (j & 1) * 512 + tid;
            const int r = qq >> 3;          // row 0..127
            const int cch = qq & 7;         // 16B chunk within 128B row
            const __half* g;
            if      (tile == 0) g = gsrc0 + (size_t)r * Kdim + kt + cch * 8;
            else if (tile == 1) g = gsrc1 + (size_t)r * Kdim + kt + cch * 8;
            else if (tile == 2) g = gsrc2 + (size_t)r * Kdim + kt + cch * 8;
            else                g = gsrc3 + (size_t)r * Kdim + kt + cch * 8;
            cp16(sbase + buf * BUFB + tile * TILEB + r * ROWB + cch * 16, g);
        }
        cp_commit();
    };

    issue(0, 0);
    if (nTiles > 1) issue(1, HBK);

    // per-lane ldmatrix address components (loop invariant)
    const int arow  = wm * 32 + (lane & 15);
    const int akof  = (lane >> 4) * 8;
    // B x4 mapping: mat0/1 = n-rows p*16+0..7 (k-low/k-high), mat2/3 = rows +8
    const int brow4 = wn * 32 + ((lane >> 4) & 1) * 8 + (lane & 7);
    const int bk4   = ((lane >> 3) & 1) * 8;

    for (int t = 0; t < nTiles; ++t) {
        if (t + 2 < nTiles) {
            issue((t + 2) % NSTAGE, (t + 2) * HBK);
            cp_wait<2>();
        } else if (t + 1 < nTiles) {
            cp_wait<1>();
        } else {
            cp_wait<0>();
        }
        __syncthreads();

        const uint32_t bufb = sbase + (t % NSTAGE) * BUFB;
        const uint32_t aBhi = bufb;
        const uint32_t aBlo = bufb + TILEB;
        const uint32_t bBhi = bufb + 2 * TILEB;
        const uint32_t bBlo = bufb + 3 * TILEB;

#pragma unroll
        for (int ks = 0; ks < HBK; ks += 16) {
            uint32_t ah[2][4], al[2][4], bh[4][2], bl[4][2];
#pragma unroll
            for (int am = 0; am < 2; am++) {
                const uint32_t off = (uint32_t)(arow + am * 16) * ROWB + (ks + akof) * 2;
                ldsm_x4(ah[am], aBhi + off);
                ldsm_x4(al[am], aBlo + off);
            }
#pragma unroll
            for (int p = 0; p < 2; p++) {
                const uint32_t off = (uint32_t)(brow4 + p * 16) * ROWB + (ks + bk4) * 2;
                ldsm_x4(&bh[p * 2][0], bBhi + off);
                ldsm_x4(&bl[p * 2][0], bBlo + off);
            }
            // hi*hi
#pragma unroll
            for (int am = 0; am < 2; am++)
#pragma unroll
                for (int bn = 0; bn < 4; bn++)
                    mma16816(acc[am][bn], ah[am], bh[bn]);
            // hi*lo
#pragma unroll
            for (int am = 0; am < 2; am++)
#pragma unroll
                for (int bn = 0; bn < 4; bn++)
                    mma16816(acc[am][bn], ah[am], bl[bn]);
            // lo*hi
#pragma unroll
            for (int am = 0; am < 2; am++)
#pragma unroll
                for (int bn = 0; bn < 4; bn++)
                    mma16816(acc[am][bn], al[am], bh[bn]);
        }
        __syncthreads();
    }

    // ---- epilogue ----
#pragma unroll
    for (int am = 0; am < 2; am++) {
#pragma unroll
        for (int bn = 0; bn < 4; bn++) {
            const int row = m0 + wm * 32 + am * 16 + (lane >> 2);
            const int col = n0 + wn * 32 + bn * 8 + (lane & 3) * 2;
            float v[4];
#pragma unroll
            for (int k = 0; k < 4; k++) v[k] = acc[am][bn][k] * scale;
            if (bias) {
                const float bx = bias[col], by = bias[col + 1];
                v[0] += bx; v[1] += by; v[2] += bx; v[3] += by;
            }
            if (ACT == 1) {
#pragma unroll
                for (int k = 0; k < 4; k++) v[k] = gelu_exact(v[k]);
            }
            if (OUT_SPLIT == 1) {
#pragma unroll
                for (int half_row = 0; half_row < 2; half_row++) {
                    const size_t base = (size_t)(row + half_row * 8) * ldc + col;
                    const float v0 = v[half_row * 2], v1 = v[half_row * 2 + 1];
                    const __half h0 = __float2half_rn(v0);
                    const __half h1 = __float2half_rn(v1);
                    __half2 hhi = __halves2half2(h0, h1);
                    __half2 hlo = __halves2half2(__float2half_rn(v0 - __half2float(h0)),
                                                 __float2half_rn(v1 - __half2float(h1)));
                    *(__half2*)(Chi + base) = hhi;
                    *(__half2*)(Clo + base) = hlo;
                }
            } else {
                *(float2*)(Cf + (size_t)row * ldc + col) = make_float2(v[0], v[1]);
                *(float2*)(Cf + (size_t)(row + 8) * ldc + col) = make_float2(v[2], v[3]);
            }
        }
    }
}

// ---------------- fp32 -> fp16 hi/lo split for both embeddings in one launch ----------------
__global__ __launch_bounds__(256)
void split2_kernel(const float* __restrict__ ina, const float* __restrict__ inb,
                   __half* __restrict__ hi, __half* __restrict__ lo, int n)
{
    int i = blockIdx.x * 256 + threadIdx.x;
    float x;
    if (i < n)            x = ina[i];
    else if (i < 2 * n)   x = inb[i - n];
    else return;
    __half h = __float2half_rn(x);
    hi[i] = h;
    lo[i] = __float2half_rn(x - __half2float(h));
}

// ---------------- W [K,N] fp32 -> transposed [N,K] hi/lo half splits ----------------
__global__ void splitT_kernel(const float* __restrict__ in,
                              __half* __restrict__ hi, __half* __restrict__ lo)
{
    __shared__ float tile[32][33];
    const int x = blockIdx.x * 32 + threadIdx.x;   // N index in input
#pragma unroll
    for (int dy = threadIdx.y; dy < 32; dy += 8)
        tile[dy][threadIdx.x] = in[(size_t)(blockIdx.y * 32 + dy) * DD + x];
    __syncthreads();
    const int k = blockIdx.y * 32 + threadIdx.x;   // K index in output (contiguous)
#pragma unroll
    for (int dy = threadIdx.y; dy < 32; dy += 8) {
        const int n = blockIdx.x * 32 + dy;
        const float v = tile[threadIdx.x][dy];
        const __half h = __float2half_rn(v);
        hi[(size_t)n * DD + k] = h;
        lo[(size_t)n * DD + k] = __float2half_rn(v - __half2float(h));
    }
}

// ---------------- fused Sinkhorn iteration ----------------
// Variable rows per block: blocks [0,SINK_FULL) take 14 rows, rest 13 (592 = 4 waves).
// FIRST=1: max-tracked row LSE + per-column register LSE accumulators.
// FIRST=0: plain exp-sums; next row's loads prefetched into the dead v registers
// before the reduction barrier so DRAM latency hides under the reduce phase.
template <int FIRST>
__global__ __launch_bounds__(256)
void sink_iter_kernel(const float* __restrict__ S, float* __restrict__ r,
                      const float* __restrict__ c,
                      float* __restrict__ p1, float* __restrict__ p2)
{
    __shared__ float sc[NR];
    __shared__ float red[2][8];
    const int tid = threadIdx.x;
    const int bid = blockIdx.x;

    if (!FIRST) {
        for (int j = tid; j < NR / 4; j += 256)
            ((float4*)sc)[j] = ((const float4*)c)[j];
        __syncthreads();
    }

    float4 accs[8];
    float4 accm[8];
#pragma unroll
    for (int k = 0; k < 8; ++k) {
        accs[k] = make_float4(0.f, 0.f, 0.f, 0.f);
        if (FIRST) accm[k] = make_float4(-INFINITY, -INFINITY, -INFINITY, -INFINITY);
    }

    const int nrows = 13 + (bid < SINK_FULL ? 1 : 0);
    const int i0 = (bid < SINK_FULL) ? bid * 14 : SINK_FULL * 14 + (bid - SINK_FULL) * 13;

    if (FIRST) {
        for (int ii = 0; ii < nrows; ++ii) {
            const int i = i0 + ii;
            const float4* row = (const float4*)(S + (size_t)i * NR);
            float4 v[8];
#pragma unroll
            for (int k = 0; k < 8; ++k) v[k] = row[tid + 256 * k];

            float mx = -INFINITY;
#pragma unroll
            for (int k = 0; k < 8; ++k)
                mx = fmaxf(mx, fmaxf(fmaxf(v[k].x, v[k].y), fmaxf(v[k].z, v[k].w)));
#pragma unroll
            for (int o = 16; o > 0; o >>= 1) mx = fmaxf(mx, __shfl_xor_sync(0xffffffffu, mx, o));
            if ((tid & 31) == 0) red[0][tid >> 5] = mx;
            __syncthreads();
            mx = red[0][0];
#pragma unroll
            for (int w = 1; w < 8; ++w) mx = fmaxf(mx, red[0][w]);
            __syncthreads();
            float s = 0.0f;
#pragma unroll
            for (int k = 0; k < 8; ++k) {
                s += __expf(v[k].x - mx) + __expf(v[k].y - mx)
                   + __expf(v[k].z - mx) + __expf(v[k].w - mx);
            }
#pragma unroll
            for (int o = 16; o > 0; o >>= 1) s += __shfl_xor_sync(0xffffffffu, s, o);
            if ((tid & 31) == 0) red[1][tid >> 5] = s;
            __syncthreads();
            float t = red[1][0];
#pragma unroll
            for (int w = 1; w < 8; ++w) t += red[1][w];
            const float ri = mx + logf(t);
            if (tid == 0) r[i] = ri;
            __syncthreads();
#pragma unroll
            for (int k = 0; k < 8; ++k) {
                lse_add(accm[k].x, accs[k].x, v[k].x - ri);
                lse_add(accm[k].y, accs[k].y, v[k].y - ri);
                lse_add(accm[k].z, accs[k].z, v[k].z - ri);
                lse_add(accm[k].w, accs[k].w, v[k].w - ri);
            }
        }
    } else {
        float4 v[8];
        {
            const float4* row0 = (const float4*)(S + (size_t)i0 * NR);
#pragma unroll
            for (int k = 0; k < 8; ++k) v[k] = row0[tid + 256 * k];
        }
        for (int ii = 0; ii < nrows; ++ii) {
            const int i = i0 + ii;
            const float ri = __ldg(&r[i]);
            float4 e[8];
            float s = 0.0f;
#pragma unroll
            for (int k = 0; k < 8; ++k) {
                float4 cc = ((const float4*)sc)[tid + 256 * k];
                e[k].x = __expf(v[k].x - cc.x - ri);
                e[k].y = __expf(v[k].y - cc.y - ri);
                e[k].z = __expf(v[k].z - cc.z - ri);
                e[k].w = __expf(v[k].w - cc.w - ri);
                s += (e[k].x + e[k].y) + (e[k].z + e[k].w);
            }
            // v is dead: prefetch next row into it before the barriers
            if (ii + 1 < nrows) {
                const float4* rn = (const float4*)(S + (size_t)(i + 1) * NR);
#pragma unroll
                for (int k = 0; k < 8; ++k) v[k] = rn[tid + 256 * k];
            }
#pragma unroll
            for (int o = 16; o > 0; o >>= 1) s += __shfl_xor_sync(0xffffffffu, s, o);
            if ((tid & 31) == 0) red[ii & 1][tid >> 5] = s;
            __syncthreads();
            float t = red[ii & 1][0];
#pragma unroll
            for (int w = 1; w < 8; ++w) t += red[ii & 1][w];
            if (tid == 0) r[i] = ri + logf(t);
            // no second barrier: red is double-buffered by (ii & 1)
            const float inv = 1.0f / t;
#pragma unroll
            for (int k = 0; k < 8; ++k) {
                accs[k].x += e[k].x * inv;
                accs[k].y += e[k].y * inv;
                accs[k].z += e[k].z * inv;
                accs[k].w += e[k].w * inv;
            }
        }
    }
    float4* o1 = (float4*)(p1 + (size_t)bid * NR);
    if (FIRST) {
        float4* o2 = (float4*)(p2 + (size_t)bid * NR);
#pragma unroll
        for (int k = 0; k < 8; ++k) { o1[tid + 256 * k] = accm[k]; o2[tid + 256 * k] = accs[k]; }
    } else {
#pragma unroll
        for (int k = 0; k < 8; ++k) o1[tid + 256 * k] = accs[k];
    }
}

// ---------------- combine iter-1 column LSE partials: c = m + log(s) ----------------
__global__ __launch_bounds__(256)
void first_combine_kernel(const float* __restrict__ pm, const float* __restrict__ ps,
                          float* __restrict__ c)
{
    __shared__ float sm[4][64], ss[4][64];
    const int tid = threadIdx.x;
    const int jj  = tid & 63;
    const int sub = tid >> 6;
    const int j   = blockIdx.x * 64 + jj;
    float m = -INFINITY, s = 0.0f;
    for (int b = sub * (SINK_NBLK / 4); b < (sub + 1) * (SINK_NBLK / 4); ++b)
        lse_merge(m, s, pm[(size_t)b * NR + j], ps[(size_t)b * NR + j]);
    sm[sub][jj] = m; ss[sub][jj] = s;
    __syncthreads();
    if (tid < 64) {
        float m0 = sm[0][tid], s0 = ss[0][tid];
        lse_merge(m0, s0, sm[1][tid], ss[1][tid]);
        lse_merge(m0, s0, sm[2][tid], ss[2][tid]);
        lse_merge(m0, s0, sm[3][tid], ss[3][tid]);
        c[blockIdx.x * 64 + tid] = m0 + logf(s0);
    }
}

// ---------------- combine plain column partials: c += log(sum) ----------------
__global__ __launch_bounds__(256)
void sink_combine_kernel(const float* __restrict__ part, float* __restrict__ c)
{
    __shared__ float ss[4][64];
    const int tid = threadIdx.x;
    const int jj  = tid & 63;
    const int sub = tid >> 6;
    const int j   = blockIdx.x * 64 + jj;
    float s = 0.0f;
    for (int b = sub * (SINK_NBLK / 4); b < (sub + 1) * (SINK_NBLK / 4); ++b)
        s += part[(size_t)b * NR + j];
    ss[sub][jj] = s;
    __syncthreads();
    if (tid < 64) {
        float t = ss[0][tid] + ss[1][tid] + ss[2][tid] + ss[3][tid];
        c[blockIdx.x * 64 + tid] += logf(t);
    }
}

// ---------------- output: out = exp(S - r_i - c_j), row-blocked ----------------
__global__ __launch_bounds__(256)
void out_exp_kernel(const float* __restrict__ S, const float* __restrict__ r,
                    const float* __restrict__ c, float* __restrict__ out)
{
    const int tid = threadIdx.x;
    const float4* c4 = (const float4*)c;
#pragma unroll
    for (int rr = 0; rr < 4; ++rr) {
        const int i = blockIdx.x * 4 + rr;
        const float ri = __ldg(&r[i]);
        const float4* row = (const float4*)(S + (size_t)i * NR);
        float4* orow = (float4*)(out + (size_t)i * NR);
#pragma unroll
        for (int k = 0; k < 8; ++k) {
            const int j = tid + 256 * k;
            float4 v  = row[j];
            float4 cc = c4[j];
            float4 o;
            o.x = __expf(v.x - ri - cc.x);
            o.y = __expf(v.y - ri - cc.y);
            o.z = __expf(v.z - ri - cc.z);
            o.w = __expf(v.w - ri - cc.w);
            orow[j] = o;
        }
    }
}

// ---------------- launch ----------------
extern "C" void kernel_launch(void* const* d_in, const int* in_sizes, int n_in,
                              void* d_out, int out_size)
{
    const float* emb_a = (const float*)d_in[0];
    const float* emb_b = (const float*)d_in[1];
    const float* W1    = (const float*)d_in[2];
    const float* b1    = (const float*)d_in[3];
    const float* W2    = (const float*)d_in[4];
    const float* b2    = (const float*)d_in[5];
    float* out = (float*)d_out;

    float *scores, *r, *c, *pm, *ps;
    __half *x_hi, *x_lo, *h_hi, *h_lo, *ab_hi, *ab_lo;
    __half *w1_hi, *w1_lo, *w2_hi, *w2_lo;
    cudaGetSymbolAddress((void**)&scores, g_scores);
    cudaGetSymbolAddress((void**)&x_hi, g_x_hi);
    cudaGetSymbolAddress((void**)&x_lo, g_x_lo);
    cudaGetSymbolAddress((void**)&h_hi, g_h_hi);
    cudaGetSymbolAddress((void**)&h_lo, g_h_lo);
    cudaGetSymbolAddress((void**)&ab_hi, g_ab_hi);
    cudaGetSymbolAddress((void**)&ab_lo, g_ab_lo);
    cudaGetSymbolAddress((void**)&w1_hi, g_w1_hi);
    cudaGetSymbolAddress((void**)&w1_lo, g_w1_lo);
    cudaGetSymbolAddress((void**)&w2_hi, g_w2_hi);
    cudaGetSymbolAddress((void**)&w2_lo, g_w2_lo);
    cudaGetSymbolAddress((void**)&r,  g_r);
    cudaGetSymbolAddress((void**)&c,  g_c);
    cudaGetSymbolAddress((void**)&pm, g_pm);
    cudaGetSymbolAddress((void**)&ps, g_ps);

    cudaFuncSetAttribute(hmma_kernel<1, 1>,
                         cudaFuncAttributeMaxDynamicSharedMemorySize, SMEM_HMMA);
    cudaFuncSetAttribute(hmma_kernel<0, 1>,
                         cudaFuncAttributeMaxDynamicSharedMemorySize, SMEM_HMMA);
    cudaFuncSetAttribute(hmma_kernel<0, 0>,
                         cudaFuncAttributeMaxDynamicSharedMemorySize, SMEM_HMMA);

    const int nel = NR * DD;

    // weight split + transpose to [N, K]
    splitT_kernel<<<dim3(32, 32), dim3(32, 8)>>>(W1, w1_hi, w1_lo);
    splitT_kernel<<<dim3(32, 32), dim3(32, 8)>>>(W2, w2_hi, w2_lo);

    // both embeddings into one [2*NR, DD] split buffer (single launch)
    split2_kernel<<<2 * nel / 256, 256>>>(emb_a, emb_b, x_hi, x_lo, nel);

    // batched projections: [2*NR, DD] once through each layer
    const dim3 gProj(DD / 128, 2 * NR / 128);   // (8, 128)
    hmma_kernel<1, 1><<<gProj, 512, SMEM_HMMA>>>(x_hi, x_lo, w1_hi, w1_lo, b1,
                                                 nullptr, h_hi, h_lo, DD, DD, 1.0f);
    hmma_kernel<0, 1><<<gProj, 512, SMEM_HMMA>>>(h_hi, h_lo, w2_hi, w2_lo, b2,
                                                 nullptr, ab_hi, ab_lo, DD, DD, 1.0f);

    // scores = 20 * a @ b^T  (a = ab rows 0..NR-1, b = rows NR..2NR-1)
    const dim3 gScore(NR / 128, NR / 128);      // (64, 64)
    hmma_kernel<0, 0><<<gScore, 512, SMEM_HMMA>>>(ab_hi, ab_lo,
                                                  ab_hi + (size_t)nel, ab_lo + (size_t)nel,
                                                  nullptr, scores, nullptr, nullptr,
                                                  NR, DD, INV_TEMP);

    // Sinkhorn iteration 1: fused row LSE + column LSE partials (underflow-safe)
    sink_iter_kernel<1><<<SINK_NBLK, 256>>>(scores, r, nullptr, pm, ps);
    first_combine_kernel<<<NR / 64, 256>>>(pm, ps, c);

    // iterations 2..20: fused single-pass with plain sums + row prefetch
    for (int it = 1; it < ITERS; ++it) {
        sink_iter_kernel<0><<<SINK_NBLK, 256>>>(scores, r, c, pm, nullptr);
        sink_combine_kernel<<<NR / 64, 256>>>(pm, c);
    }

    // final output
    out_exp_kernel<<<NR / 4, 256>>>(scores, r, c, out);
}

// round 15
// speedup vs baseline: 1.8913x; 1.0719x over previous
#include <cuda_runtime.h>
#include <cuda_fp16.h>
#include <math.h>
#include <stdint.h>

// Problem constants
#define NR 8192
#define DD 1024
#define ITERS 20
#define INV_TEMP 20.0f

// Sinkhorn blocking: 296 = 2 resident CTAs x 148 SMs -> one clean wave
#define SINK_NBLK 296
#define SINK_FULL 200          // blocks 0..199 take 28 rows, rest take 27  (200*28+96*27=8192)

// HMMA tiling: BM=BN=128, BK=64, 512 threads, 16 warps (4 M x 4 N), warp tile 32x32
#define HBK 64
#define ROWB 144                      // padded row stride in bytes (64 halfs + 16 pad)
#define TILEB (128 * ROWB)            // 18432 B per operand tile
#define BUFB (4 * TILEB)              // 73728 B per stage (Ahi,Alo,Bhi,Blo)
#define NSTAGE 3
#define SMEM_HMMA (NSTAGE * BUFB)     // 221184 B triple buffered

// ---------------- device scratch (static, no allocation) ----------------
__device__ float g_scores[(size_t)NR * NR];   // 256 MB
__device__ __half g_x_hi[(size_t)2 * NR * DD];
__device__ __half g_x_lo[(size_t)2 * NR * DD];
__device__ __half g_h_hi[(size_t)2 * NR * DD];
__device__ __half g_h_lo[(size_t)2 * NR * DD];
__device__ __half g_ab_hi[(size_t)2 * NR * DD];   // rows 0..NR-1 = a, NR.. = b
__device__ __half g_ab_lo[(size_t)2 * NR * DD];
__device__ __half g_w1_hi[(size_t)DD * DD];
__device__ __half g_w1_lo[(size_t)DD * DD];
__device__ __half g_w2_hi[(size_t)DD * DD];
__device__ __half g_w2_lo[(size_t)DD * DD];
__device__ float g_r[NR];
__device__ float g_c[NR];
__device__ float g_pm[(size_t)SINK_NBLK * NR];
__device__ float g_ps[(size_t)SINK_NBLK * NR];

// ---------------- small helpers ----------------
__device__ __forceinline__ uint32_t smem_to_u32(const void* smem_ptr) {
    uint32_t addr;
    asm("{ .reg .u64 tmp; cvta.to.shared.u64 tmp, %1; cvt.u32.u64 %0, tmp; }"
        : "=r"(addr) : "l"(smem_ptr));
    return addr;
}
__device__ __forceinline__ void cp16(uint32_t saddr, const void* g) {
    asm volatile("cp.async.cg.shared.global [%0], [%1], 16;" :: "r"(saddr), "l"(g));
}
__device__ __forceinline__ void cp_commit() {
    asm volatile("cp.async.commit_group;");
}
template <int N> __device__ __forceinline__ void cp_wait() {
    asm volatile("cp.async.wait_group %0;" :: "n"(N));
}
__device__ __forceinline__ void ldsm_x4(uint32_t* r, uint32_t addr) {
    asm volatile("ldmatrix.sync.aligned.m8n8.x4.shared.b16 {%0,%1,%2,%3}, [%4];"
                 : "=r"(r[0]), "=r"(r[1]), "=r"(r[2]), "=r"(r[3]) : "r"(addr));
}
__device__ __forceinline__ void mma16816(float* c, const uint32_t* a, const uint32_t* b) {
    asm volatile(
        "mma.sync.aligned.m16n8k16.row.col.f32.f16.f16.f32 "
        "{%0,%1,%2,%3}, {%4,%5,%6,%7}, {%8,%9}, {%0,%1,%2,%3};"
        : "+f"(c[0]), "+f"(c[1]), "+f"(c[2]), "+f"(c[3])
        : "r"(a[0]), "r"(a[1]), "r"(a[2]), "r"(a[3]), "r"(b[0]), "r"(b[1]));
}
__device__ __forceinline__ float gelu_exact(float x) {
    return 0.5f * x * (1.0f + erff(x * 0.70710678118654752440f));
}
__device__ __forceinline__ void lse_add(float& m, float& s, float v) {
    if (v <= m) { s += __expf(v - m); }
    else        { s = s * __expf(m - v) + 1.0f; m = v; }
}
__device__ __forceinline__ void lse_merge(float& m1, float& s1, float m2, float s2) {
    if (m2 == -INFINITY) return;
    if (m1 == -INFINITY) { m1 = m2; s1 = s2; return; }
    if (m2 <= m1) { s1 += s2 * __expf(m2 - m1); }
    else { s1 = s1 * __expf(m1 - m2) + s2; m1 = m2; }
}

// ---------------- HMMA GEMM: C = epilogue(scale*(A @ B^T) [+ bias]) ----------------
// 512 threads, 16 warps (4x4), warp tile 32x32.
// Inner K-group reordered: ldsm(hi) -> hh MMAs -> ldsm(lo) -> hl/lh MMAs,
// halving exposed LDSM latency at each group boundary.
template <int ACT, int OUT_SPLIT>
__global__ __launch_bounds__(512)
void hmma_kernel(const __half* __restrict__ Ah, const __half* __restrict__ Al,
                 const __half* __restrict__ Bh, const __half* __restrict__ Bl,
                 const float* __restrict__ bias,
                 float* __restrict__ Cf, __half* __restrict__ Chi, __half* __restrict__ Clo,
                 int ldc, int Kdim, float scale)
{
    extern __shared__ __align__(16) char smem[];
    const uint32_t sbase = smem_to_u32(smem);
    const int tid  = threadIdx.x;
    const int warp = tid >> 5;
    const int lane = tid & 31;
    const int wm = warp >> 2;       // 0..3 (32-row slab)
    const int wn = warp & 3;        // 0..3 (32-col slab)

    const int m0 = blockIdx.y * 128;
    const int n0 = blockIdx.x * 128;

    const __half* gsrc0 = Ah + (size_t)m0 * Kdim;
    const __half* gsrc1 = Al + (size_t)m0 * Kdim;
    const __half* gsrc2 = Bh + (size_t)n0 * Kdim;
    const __half* gsrc3 = Bl + (size_t)n0 * Kdim;

    float acc[2][4][4];
#pragma unroll
    for (int i = 0; i < 2; i++)
#pragma unroll
        for (int j = 0; j < 4; j++)
#pragma unroll
            for (int k = 0; k < 4; k++) acc[i][j][k] = 0.0f;

    const int nTiles = Kdim / HBK;

    // ---- async tile loader: 8 x 16B chunks per thread per stage ----
    auto issue = [&](int buf, int kt) {
#pragma unroll
        for (int j = 0; j < 8; j++) {
            const int tile = j >> 1;
            const int qq = (j & 1) * 512 + tid;
            const int r = qq >> 3;          // row 0..127
            const int cch = qq & 7;         // 16B chunk within 128B row
            const __half* g;
            if      (tile == 0) g = gsrc0 + (size_t)r * Kdim + kt + cch * 8;
            else if (tile == 1) g = gsrc1 + (size_t)r * Kdim + kt + cch * 8;
            else if (tile == 2) g = gsrc2 + (size_t)r * Kdim + kt + cch * 8;
            else                g = gsrc3 + (size_t)r * Kdim + kt + cch * 8;
            cp16(sbase + buf * BUFB + tile * TILEB + r * ROWB + cch * 16, g);
        }
        cp_commit();
    };

    issue(0, 0);
    if (nTiles > 1) issue(1, HBK);

    // per-lane ldmatrix address components (loop invariant)
    const int arow  = wm * 32 + (lane & 15);
    const int akof  = (lane >> 4) * 8;
    // B x4 mapping: mat0/1 = n-rows p*16+0..7 (k-low/k-high), mat2/3 = rows +8
    const int brow4 = wn * 32 + ((lane >> 4) & 1) * 8 + (lane & 7);
    const int bk4   = ((lane >> 3) & 1) * 8;

    for (int t = 0; t < nTiles; ++t) {
        if (t + 2 < nTiles) {
            issue((t + 2) % NSTAGE, (t + 2) * HBK);
            cp_wait<2>();
        } else if (t + 1 < nTiles) {
            cp_wait<1>();
        } else {
            cp_wait<0>();
        }
        __syncthreads();

        const uint32_t bufb = sbase + (t % NSTAGE) * BUFB;
        const uint32_t aBhi = bufb;
        const uint32_t aBlo = bufb + TILEB;
        const uint32_t bBhi = bufb + 2 * TILEB;
        const uint32_t bBlo = bufb + 3 * TILEB;

#pragma unroll
        for (int ks = 0; ks < HBK; ks += 16) {
            uint32_t ah[2][4], al[2][4], bh[4][2], bl[4][2];
            // hi fragments first
#pragma unroll
            for (int am = 0; am < 2; am++)
                ldsm_x4(ah[am], aBhi + (uint32_t)(arow + am * 16) * ROWB + (ks + akof) * 2);
#pragma unroll
            for (int p = 0; p < 2; p++)
                ldsm_x4(&bh[p * 2][0], bBhi + (uint32_t)(brow4 + p * 16) * ROWB + (ks + bk4) * 2);
            // hi*hi (only depends on the 4 LDSM above)
#pragma unroll
            for (int am = 0; am < 2; am++)
#pragma unroll
                for (int bn = 0; bn < 4; bn++)
                    mma16816(acc[am][bn], ah[am], bh[bn]);
            // lo fragments issue under the hh MMA burst
#pragma unroll
            for (int am = 0; am < 2; am++)
                ldsm_x4(al[am], aBlo + (uint32_t)(arow + am * 16) * ROWB + (ks + akof) * 2);
#pragma unroll
            for (int p = 0; p < 2; p++)
                ldsm_x4(&bl[p * 2][0], bBlo + (uint32_t)(brow4 + p * 16) * ROWB + (ks + bk4) * 2);
            // hi*lo
#pragma unroll
            for (int am = 0; am < 2; am++)
#pragma unroll
                for (int bn = 0; bn < 4; bn++)
                    mma16816(acc[am][bn], ah[am], bl[bn]);
            // lo*hi
#pragma unroll
            for (int am = 0; am < 2; am++)
#pragma unroll
                for (int bn = 0; bn < 4; bn++)
                    mma16816(acc[am][bn], al[am], bh[bn]);
        }
        __syncthreads();
    }

    // ---- epilogue ----
#pragma unroll
    for (int am = 0; am < 2; am++) {
#pragma unroll
        for (int bn = 0; bn < 4; bn++) {
            const int row = m0 + wm * 32 + am * 16 + (lane >> 2);
            const int col = n0 + wn * 32 + bn * 8 + (lane & 3) * 2;
            float v[4];
#pragma unroll
            for (int k = 0; k < 4; k++) v[k] = acc[am][bn][k] * scale;
            if (bias) {
                const float bx = bias[col], by = bias[col + 1];
                v[0] += bx; v[1] += by; v[2] += bx; v[3] += by;
            }
            if (ACT == 1) {
#pragma unroll
                for (int k = 0; k < 4; k++) v[k] = gelu_exact(v[k]);
            }
            if (OUT_SPLIT == 1) {
#pragma unroll
                for (int half_row = 0; half_row < 2; half_row++) {
                    const size_t base = (size_t)(row + half_row * 8) * ldc + col;
                    const float v0 = v[half_row * 2], v1 = v[half_row * 2 + 1];
                    const __half h0 = __float2half_rn(v0);
                    const __half h1 = __float2half_rn(v1);
                    __half2 hhi = __halves2half2(h0, h1);
                    __half2 hlo = __halves2half2(__float2half_rn(v0 - __half2float(h0)),
                                                 __float2half_rn(v1 - __half2float(h1)));
                    *(__half2*)(Chi + base) = hhi;
                    *(__half2*)(Clo + base) = hlo;
                }
            } else {
                *(float2*)(Cf + (size_t)row * ldc + col) = make_float2(v[0], v[1]);
                *(float2*)(Cf + (size_t)(row + 8) * ldc + col) = make_float2(v[2], v[3]);
            }
        }
    }
}

// ---------------- fp32 -> fp16 hi/lo split for both embeddings in one launch ----------------
__global__ __launch_bounds__(256)
void split2_kernel(const float* __restrict__ ina, const float* __restrict__ inb,
                   __half* __restrict__ hi, __half* __restrict__ lo, int n)
{
    int i = blockIdx.x * 256 + threadIdx.x;
    float x;
    if (i < n)            x = ina[i];
    else if (i < 2 * n)   x = inb[i - n];
    else return;
    __half h = __float2half_rn(x);
    hi[i] = h;
    lo[i] = __float2half_rn(x - __half2float(h));
}

// ---------------- W [K,N] fp32 -> transposed [N,K] hi/lo half splits ----------------
__global__ void splitT_kernel(const float* __restrict__ in,
                              __half* __restrict__ hi, __half* __restrict__ lo)
{
    __shared__ float tile[32][33];
    const int x = blockIdx.x * 32 + threadIdx.x;   // N index in input
#pragma unroll
    for (int dy = threadIdx.y; dy < 32; dy += 8)
        tile[dy][threadIdx.x] = in[(size_t)(blockIdx.y * 32 + dy) * DD + x];
    __syncthreads();
    const int k = blockIdx.y * 32 + threadIdx.x;   // K index in output (contiguous)
#pragma unroll
    for (int dy = threadIdx.y; dy < 32; dy += 8) {
        const int n = blockIdx.x * 32 + dy;
        const float v = tile[threadIdx.x][dy];
        const __half h = __float2half_rn(v);
        hi[(size_t)n * DD + k] = h;
        lo[(size_t)n * DD + k] = __float2half_rn(v - __half2float(h));
    }
}

// ---------------- fused Sinkhorn iteration ----------------
// 296 blocks (one clean 2-resident wave); blocks [0,SINK_FULL) take 28 rows, rest 27.
// FIRST=1: max-tracked row LSE + per-column register LSE accumulators.
// FIRST=0: plain exp-sums; next row prefetched into dead v registers.
template <int FIRST>
__global__ __launch_bounds__(256)
void sink_iter_kernel(const float* __restrict__ S, float* __restrict__ r,
                      const float* __restrict__ c,
                      float* __restrict__ p1, float* __restrict__ p2)
{
    __shared__ float sc[NR];
    __shared__ float red[2][8];
    const int tid = threadIdx.x;
    const int bid = blockIdx.x;

    if (!FIRST) {
        for (int j = tid; j < NR / 4; j += 256)
            ((float4*)sc)[j] = ((const float4*)c)[j];
        __syncthreads();
    }

    float4 accs[8];
    float4 accm[8];
#pragma unroll
    for (int k = 0; k < 8; ++k) {
        accs[k] = make_float4(0.f, 0.f, 0.f, 0.f);
        if (FIRST) accm[k] = make_float4(-INFINITY, -INFINITY, -INFINITY, -INFINITY);
    }

    const int nrows = 27 + (bid < SINK_FULL ? 1 : 0);
    const int i0 = (bid < SINK_FULL) ? bid * 28 : SINK_FULL * 28 + (bid - SINK_FULL) * 27;

    if (FIRST) {
        for (int ii = 0; ii < nrows; ++ii) {
            const int i = i0 + ii;
            const float4* row = (const float4*)(S + (size_t)i * NR);
            float4 v[8];
#pragma unroll
            for (int k = 0; k < 8; ++k) v[k] = row[tid + 256 * k];

            float mx = -INFINITY;
#pragma unroll
            for (int k = 0; k < 8; ++k)
                mx = fmaxf(mx, fmaxf(fmaxf(v[k].x, v[k].y), fmaxf(v[k].z, v[k].w)));
#pragma unroll
            for (int o = 16; o > 0; o >>= 1) mx = fmaxf(mx, __shfl_xor_sync(0xffffffffu, mx, o));
            if ((tid & 31) == 0) red[0][tid >> 5] = mx;
            __syncthreads();
            mx = red[0][0];
#pragma unroll
            for (int w = 1; w < 8; ++w) mx = fmaxf(mx, red[0][w]);
            __syncthreads();
            float s = 0.0f;
#pragma unroll
            for (int k = 0; k < 8; ++k) {
                s += __expf(v[k].x - mx) + __expf(v[k].y - mx)
                   + __expf(v[k].z - mx) + __expf(v[k].w - mx);
            }
#pragma unroll
            for (int o = 16; o > 0; o >>= 1) s += __shfl_xor_sync(0xffffffffu, s, o);
            if ((tid & 31) == 0) red[1][tid >> 5] = s;
            __syncthreads();
            float t = red[1][0];
#pragma unroll
            for (int w = 1; w < 8; ++w) t += red[1][w];
            const float ri = mx + logf(t);
            if (tid == 0) r[i] = ri;
            __syncthreads();
#pragma unroll
            for (int k = 0; k < 8; ++k) {
                lse_add(accm[k].x, accs[k].x, v[k].x - ri);
                lse_add(accm[k].y, accs[k].y, v[k].y - ri);
                lse_add(accm[k].z, accs[k].z, v[k].z - ri);
                lse_add(accm[k].w, accs[k].w, v[k].w - ri);
            }
        }
    } else {
        float4 v[8];
        {
            const float4* row0 = (const float4*)(S + (size_t)i0 * NR);
#pragma unroll
            for (int k = 0; k < 8; ++k) v[k] = row0[tid + 256 * k];
        }
        for (int ii = 0; ii < nrows; ++ii) {
            const int i = i0 + ii;
            const float ri = __ldg(&r[i]);
            float4 e[8];
            float s = 0.0f;
#pragma unroll
            for (int k = 0; k < 8; ++k) {
                float4 cc = ((const float4*)sc)[tid + 256 * k];
                e[k].x = __expf(v[k].x - cc.x - ri);
                e[k].y = __expf(v[k].y - cc.y - ri);
                e[k].z = __expf(v[k].z - cc.z - ri);
                e[k].w = __expf(v[k].w - cc.w - ri);
                s += (e[k].x + e[k].y) + (e[k].z + e[k].w);
            }
            // v is dead: prefetch next row into it before the barrier
            if (ii + 1 < nrows) {
                const float4* rn = (const float4*)(S + (size_t)(i + 1) * NR);
#pragma unroll
                for (int k = 0; k < 8; ++k) v[k] = rn[tid + 256 * k];
            }
#pragma unroll
            for (int o = 16; o > 0; o >>= 1) s += __shfl_xor_sync(0xffffffffu, s, o);
            if ((tid & 31) == 0) red[ii & 1][tid >> 5] = s;
            __syncthreads();
            float t = red[ii & 1][0];
#pragma unroll
            for (int w = 1; w < 8; ++w) t += red[ii & 1][w];
            if (tid == 0) r[i] = ri + logf(t);
            // no second barrier: red is double-buffered by (ii & 1)
            const float inv = 1.0f / t;
#pragma unroll
            for (int k = 0; k < 8; ++k) {
                accs[k].x += e[k].x * inv;
                accs[k].y += e[k].y * inv;
                accs[k].z += e[k].z * inv;
                accs[k].w += e[k].w * inv;
            }
        }
    }
    float4* o1 = (float4*)(p1 + (size_t)bid * NR);
    if (FIRST) {
        float4* o2 = (float4*)(p2 + (size_t)bid * NR);
#pragma unroll
        for (int k = 0; k < 8; ++k) { o1[tid + 256 * k] = accm[k]; o2[tid + 256 * k] = accs[k]; }
    } else {
#pragma unroll
        for (int k = 0; k < 8; ++k) o1[tid + 256 * k] = accs[k];
    }
}

// ---------------- combine iter-1 column LSE partials: c = m + log(s) ----------------
__global__ __launch_bounds__(256)
void first_combine_kernel(const float* __restrict__ pm, const float* __restrict__ ps,
                          float* __restrict__ c)
{
    __shared__ float sm[4][64], ss[4][64];
    const int tid = threadIdx.x;
    const int jj  = tid & 63;
    const int sub = tid >> 6;
    const int j   = blockIdx.x * 64 + jj;
    float m = -INFINITY, s = 0.0f;
    for (int b = sub * (SINK_NBLK / 4); b < (sub + 1) * (SINK_NBLK / 4); ++b)
        lse_merge(m, s, pm[(size_t)b * NR + j], ps[(size_t)b * NR + j]);
    sm[sub][jj] = m; ss[sub][jj] = s;
    __syncthreads();
    if (tid < 64) {
        float m0 = sm[0][tid], s0 = ss[0][tid];
        lse_merge(m0, s0, sm[1][tid], ss[1][tid]);
        lse_merge(m0, s0, sm[2][tid], ss[2][tid]);
        lse_merge(m0, s0, sm[3][tid], ss[3][tid]);
        c[blockIdx.x * 64 + tid] = m0 + logf(s0);
    }
}

// ---------------- combine plain column partials: c += log(sum) ----------------
__global__ __launch_bounds__(256)
void sink_combine_kernel(const float* __restrict__ part, float* __restrict__ c)
{
    __shared__ float ss[4][64];
    const int tid = threadIdx.x;
    const int jj  = tid & 63;
    const int sub = tid >> 6;
    const int j   = blockIdx.x * 64 + jj;
    float s = 0.0f;
    for (int b = sub * (SINK_NBLK / 4); b < (sub + 1) * (SINK_NBLK / 4); ++b)
        s += part[(size_t)b * NR + j];
    ss[sub][jj] = s;
    __syncthreads();
    if (tid < 64) {
        float t = ss[0][tid] + ss[1][tid] + ss[2][tid] + ss[3][tid];
        c[blockIdx.x * 64 + tid] += logf(t);
    }
}

// ---------------- output: out = exp(S - r_i - c_j), row-blocked ----------------
__global__ __launch_bounds__(256)
void out_exp_kernel(const float* __restrict__ S, const float* __restrict__ r,
                    const float* __restrict__ c, float* __restrict__ out)
{
    const int tid = threadIdx.x;
    const float4* c4 = (const float4*)c;
#pragma unroll
    for (int rr = 0; rr < 4; ++rr) {
        const int i = blockIdx.x * 4 + rr;
        const float ri = __ldg(&r[i]);
        const float4* row = (const float4*)(S + (size_t)i * NR);
        float4* orow = (float4*)(out + (size_t)i * NR);
#pragma unroll
        for (int k = 0; k < 8; ++k) {
            const int j = tid + 256 * k;
            float4 v  = row[j];
            float4 cc = c4[j];
            float4 o;
            o.x = __expf(v.x - ri - cc.x);
            o.y = __expf(v.y - ri - cc.y);
            o.z = __expf(v.z - ri - cc.z);
            o.w = __expf(v.w - ri - cc.w);
            orow[j] = o;
        }
    }
}

// ---------------- launch ----------------
extern "C" void kernel_launch(void* const* d_in, const int* in_sizes, int n_in,
                              void* d_out, int out_size)
{
    const float* emb_a = (const float*)d_in[0];
    const float* emb_b = (const float*)d_in[1];
    const float* W1    = (const float*)d_in[2];
    const float* b1    = (const float*)d_in[3];
    const float* W2    = (const float*)d_in[4];
    const float* b2    = (const float*)d_in[5];
    float* out = (float*)d_out;

    float *scores, *r, *c, *pm, *ps;
    __half *x_hi, *x_lo, *h_hi, *h_lo, *ab_hi, *ab_lo;
    __half *w1_hi, *w1_lo, *w2_hi, *w2_lo;
    cudaGetSymbolAddress((void**)&scores, g_scores);
    cudaGetSymbolAddress((void**)&x_hi, g_x_hi);
    cudaGetSymbolAddress((void**)&x_lo, g_x_lo);
    cudaGetSymbolAddress((void**)&h_hi, g_h_hi);
    cudaGetSymbolAddress((void**)&h_lo, g_h_lo);
    cudaGetSymbolAddress((void**)&ab_hi, g_ab_hi);
    cudaGetSymbolAddress((void**)&ab_lo, g_ab_lo);
    cudaGetSymbolAddress((void**)&w1_hi, g_w1_hi);
    cudaGetSymbolAddress((void**)&w1_lo, g_w1_lo);
    cudaGetSymbolAddress((void**)&w2_hi, g_w2_hi);
    cudaGetSymbolAddress((void**)&w2_lo, g_w2_lo);
    cudaGetSymbolAddress((void**)&r,  g_r);
    cudaGetSymbolAddress((void**)&c,  g_c);
    cudaGetSymbolAddress((void**)&pm, g_pm);
    cudaGetSymbolAddress((void**)&ps, g_ps);

    cudaFuncSetAttribute(hmma_kernel<1, 1>,
                         cudaFuncAttributeMaxDynamicSharedMemorySize, SMEM_HMMA);
    cudaFuncSetAttribute(hmma_kernel<0, 1>,
                         cudaFuncAttributeMaxDynamicSharedMemorySize, SMEM_HMMA);
    cudaFuncSetAttribute(hmma_kernel<0, 0>,
                         cudaFuncAttributeMaxDynamicSharedMemorySize, SMEM_HMMA);

    const int nel = NR * DD;

    // weight split + transpose to [N, K]
    splitT_kernel<<<dim3(32, 32), dim3(32, 8)>>>(W1, w1_hi, w1_lo);
    splitT_kernel<<<dim3(32, 32), dim3(32, 8)>>>(W2, w2_hi, w2_lo);

    // both embeddings into one [2*NR, DD] split buffer (single launch)
    split2_kernel<<<2 * nel / 256, 256>>>(emb_a, emb_b, x_hi, x_lo, nel);

    // batched projections: [2*NR, DD] once through each layer
    const dim3 gProj(DD / 128, 2 * NR / 128);   // (8, 128)
    hmma_kernel<1, 1><<<gProj, 512, SMEM_HMMA>>>(x_hi, x_lo, w1_hi, w1_lo, b1,
                                                 nullptr, h_hi, h_lo, DD, DD, 1.0f);
    hmma_kernel<0, 1><<<gProj, 512, SMEM_HMMA>>>(h_hi, h_lo, w2_hi, w2_lo, b2,
                                                 nullptr, ab_hi, ab_lo, DD, DD, 1.0f);

    // scores = 20 * a @ b^T  (a = ab rows 0..NR-1, b = rows NR..2NR-1)
    const dim3 gScore(NR / 128, NR / 128);      // (64, 64)
    hmma_kernel<0, 0><<<gScore, 512, SMEM_HMMA>>>(ab_hi, ab_lo,
                                                  ab_hi + (size_t)nel, ab_lo + (size_t)nel,
                                                  nullptr, scores, nullptr, nullptr,
                                                  NR, DD, INV_TEMP);

    // Sinkhorn iteration 1: fused row LSE + column LSE partials (underflow-safe)
    sink_iter_kernel<1><<<SINK_NBLK, 256>>>(scores, r, nullptr, pm, ps);
    first_combine_kernel<<<NR / 64, 256>>>(pm, ps, c);

    // iterations 2..20: fused single-pass with plain sums + row prefetch
    for (int it = 1; it < ITERS; ++it) {
        sink_iter_kernel<0><<<SINK_NBLK, 256>>>(scores, r, c, pm, nullptr);
        sink_combine_kernel<<<NR / 64, 256>>>(pm, c);
    }

    // final output
    out_exp_kernel<<<NR / 4, 256>>>(scores, r, c, out);
}